// round 1
// baseline (speedup 1.0000x reference)
#include <cuda_runtime.h>
#include <math.h>

#define B 64
#define NK 2048
#define HID 1024
#define EMB 512
#define KEY 512
#define VOCAB 50257

#define O_OFF (B*VOCAB)                 // 3216448
#define A_OFF (O_OFF + B*HID)           // 3281984

// ---------------- scratch (device globals; no allocation allowed) ----------
__device__ float g_qw[B*HID];           // Q@Wq + bk
__device__ float g_scores[B*NK];
__device__ float g_x[B*(EMB+KEY)];      // [emb | context], 64 x 1024
__device__ float g_h[B*HID];            // h_new
__device__ float g_lse[B];

// ---------------- kernel 1: qw = Q @ Wq + bk -------------------------------
__global__ void __launch_bounds__(256) k_qw(const float* __restrict__ hidden,
                                            const float* __restrict__ Wq,
                                            const float* __restrict__ bk) {
    int h = blockIdx.x * 256 + threadIdx.x;   // 4 blocks in x cover HID
    int b = blockIdx.y;
    __shared__ float q_s[HID];
    for (int i = threadIdx.x; i < HID; i += 256) q_s[i] = hidden[b*HID + i];
    __syncthreads();
    float acc = bk[h];
    #pragma unroll 8
    for (int k = 0; k < HID; k++)
        acc = fmaf(q_s[k], Wq[(size_t)k*HID + h], acc);
    g_qw[b*HID + h] = acc;
}

// ---------------- kernel 2: fused feat GEMM + tanh + score reduce ----------
// scores[b,n] = sum_h v[h] * tanh( sum_k ann[b,n,k]*Wk[k,h] + qw[b,h] )
// tile: 64 rows x 64 cols, K-tile 16, 256 threads, 4x4 microtile.
__global__ void __launch_bounds__(256) k_feat(const float* __restrict__ ann,
                                              const float* __restrict__ Wk,
                                              const float* __restrict__ v_attn) {
    const int tile = blockIdx.x;          // 2048 tiles
    const int b    = tile >> 5;           // 32 tiles of 64 rows per batch
    const int row0 = (tile & 31) * 64;
    const float* A = ann + ((size_t)b * NK + row0) * KEY;

    __shared__ float As[16][65];          // [k][m], padded: conflict-free writes
    __shared__ float Bs[16][64];          // [k][n], float4 read/write
    __shared__ float s_score[64];

    const int tid = threadIdx.x;
    const int tx = tid & 15;              // n micro index
    const int ty = tid >> 4;              // m micro index
    const int lr = tid >> 2;              // load row (0..63)
    const int lk4 = (tid & 3) * 4;        // load k offset {0,4,8,12}
    const int lkk = tid >> 4;             // B-load k (0..15)
    const int ln4 = (tid & 15) * 4;       // B-load n offset

    if (tid < 64) s_score[tid] = 0.f;

    for (int nc = 0; nc < HID; nc += 64) {
        float acc[4][4];
        #pragma unroll
        for (int i = 0; i < 4; i++)
            #pragma unroll
            for (int j = 0; j < 4; j++) acc[i][j] = 0.f;

        for (int kt = 0; kt < KEY; kt += 16) {
            float4 av = *(const float4*)(A + (size_t)lr*KEY + kt + lk4);
            As[lk4+0][lr] = av.x; As[lk4+1][lr] = av.y;
            As[lk4+2][lr] = av.z; As[lk4+3][lr] = av.w;
            float4 bv = *(const float4*)(Wk + (size_t)(kt+lkk)*HID + nc + ln4);
            *(float4*)&Bs[lkk][ln4] = bv;
            __syncthreads();
            #pragma unroll
            for (int kk = 0; kk < 16; kk++) {
                float a[4];
                #pragma unroll
                for (int i = 0; i < 4; i++) a[i] = As[kk][ty*4+i];
                float4 bb = *(const float4*)&Bs[kk][tx*4];
                #pragma unroll
                for (int i = 0; i < 4; i++) {
                    acc[i][0] = fmaf(a[i], bb.x, acc[i][0]);
                    acc[i][1] = fmaf(a[i], bb.y, acc[i][1]);
                    acc[i][2] = fmaf(a[i], bb.z, acc[i][2]);
                    acc[i][3] = fmaf(a[i], bb.w, acc[i][3]);
                }
            }
            __syncthreads();
        }

        // epilogue: tanh + dot with v_attn, reduce across tx (16-lane groups)
        #pragma unroll
        for (int i = 0; i < 4; i++) {
            float p = 0.f;
            #pragma unroll
            for (int j = 0; j < 4; j++) {
                int h = nc + tx*4 + j;
                float f = tanhf(acc[i][j] + g_qw[b*HID + h]);
                p = fmaf(v_attn[h], f, p);
            }
            #pragma unroll
            for (int off = 1; off < 16; off <<= 1)
                p += __shfl_xor_sync(0xffffffffu, p, off);
            if (tx == 0) s_score[ty*4 + i] += p;   // unique owner per row: race-free
        }
    }
    __syncthreads();
    if (tid < 64) g_scores[(size_t)b*NK + row0 + tid] = s_score[tid];
}

// ---------------- kernel 3: softmax + context + build x --------------------
__global__ void __launch_bounds__(256) k_attn(const float* __restrict__ ann,
                                              const int* __restrict__ ids,
                                              const float* __restrict__ emb_table,
                                              float* __restrict__ a_out) {
    int b = blockIdx.x;
    int tid = threadIdx.x;
    __shared__ float sc[NK];
    __shared__ float red[256];

    float m = -1e30f;
    for (int i = tid; i < NK; i += 256) {
        float v = g_scores[b*NK + i];
        sc[i] = v;
        m = fmaxf(m, v);
    }
    red[tid] = m; __syncthreads();
    for (int s = 128; s; s >>= 1) { if (tid < s) red[tid] = fmaxf(red[tid], red[tid+s]); __syncthreads(); }
    m = red[0]; __syncthreads();

    float sum = 0.f;
    for (int i = tid; i < NK; i += 256) { float e = expf(sc[i] - m); sc[i] = e; sum += e; }
    red[tid] = sum; __syncthreads();
    for (int s = 128; s; s >>= 1) { if (tid < s) red[tid] += red[tid+s]; __syncthreads(); }
    float inv = 1.f / red[0];
    __syncthreads();

    for (int i = tid; i < NK; i += 256) { sc[i] *= inv; a_out[(size_t)b*NK + i] = sc[i]; }
    __syncthreads();

    // context[b,k] = sum_n a[n]*ann[b,n,k]  (two k's per thread, full-row streaming)
    const float* ab = ann + (size_t)b * NK * KEY;
    int k0 = tid, k1 = tid + 256;
    float acc0 = 0.f, acc1 = 0.f;
    for (int n = 0; n < NK; n++) {
        float an = sc[n];
        acc0 = fmaf(an, ab[(size_t)n*KEY + k0], acc0);
        acc1 = fmaf(an, ab[(size_t)n*KEY + k1], acc1);
    }
    g_x[b*(EMB+KEY) + EMB + k0] = acc0;
    g_x[b*(EMB+KEY) + EMB + k1] = acc1;

    int id = ids[b];
    for (int k = tid; k < EMB; k += 256)
        g_x[b*(EMB+KEY) + k] = emb_table[(size_t)id*EMB + k];
}

// ---------------- kernel 4: GRU cell ---------------------------------------
__global__ void __launch_bounds__(256) k_gru(const float* __restrict__ hidden,
                                             const float* __restrict__ W_ih,
                                             const float* __restrict__ W_hh,
                                             const float* __restrict__ b_ih,
                                             const float* __restrict__ b_hh,
                                             float* __restrict__ o_out) {
    int j = blockIdx.x;                    // 1024 output units
    __shared__ float w[6][HID];            // 24 KB
    for (int i = threadIdx.x; i < 3*HID; i += 256) {
        int rr = i / HID, k = i % HID;
        w[rr][k]   = W_ih[(size_t)(j + rr*HID)*HID + k];
        w[rr+3][k] = W_hh[(size_t)(j + rr*HID)*HID + k];
    }
    __syncthreads();
    int warp = threadIdx.x >> 5, lane = threadIdx.x & 31;
    for (int b = warp; b < B; b += 8) {
        const float* xb = g_x + b*(EMB+KEY);
        const float* qb = hidden + b*HID;
        float a0=0,a1=0,a2=0,a3=0,a4=0,a5=0;
        for (int k = lane; k < HID; k += 32) {
            float xv = xb[k], qv = qb[k];
            a0 = fmaf(xv, w[0][k], a0);
            a1 = fmaf(xv, w[1][k], a1);
            a2 = fmaf(xv, w[2][k], a2);
            a3 = fmaf(qv, w[3][k], a3);
            a4 = fmaf(qv, w[4][k], a4);
            a5 = fmaf(qv, w[5][k], a5);
        }
        #pragma unroll
        for (int off = 16; off; off >>= 1) {
            a0 += __shfl_xor_sync(0xffffffffu, a0, off);
            a1 += __shfl_xor_sync(0xffffffffu, a1, off);
            a2 += __shfl_xor_sync(0xffffffffu, a2, off);
            a3 += __shfl_xor_sync(0xffffffffu, a3, off);
            a4 += __shfl_xor_sync(0xffffffffu, a4, off);
            a5 += __shfl_xor_sync(0xffffffffu, a5, off);
        }
        if (lane == 0) {
            float ir = a0 + b_ih[j], iz = a1 + b_ih[j+HID], inn = a2 + b_ih[j+2*HID];
            float hr = a3 + b_hh[j], hz = a4 + b_hh[j+HID], hn = a5 + b_hh[j+2*HID];
            float rg = 1.f / (1.f + expf(-(ir + hr)));
            float zg = 1.f / (1.f + expf(-(iz + hz)));
            float ng = tanhf(inn + rg * hn);
            float q  = qb[j];
            float h  = (1.f - zg) * ng + zg * q;
            g_h[b*HID + j]  = h;
            o_out[b*HID + j] = h;
        }
    }
}

// ---------------- kernel 5: logits GEMM (64 x VOCAB, K=1024) ---------------
__global__ void __launch_bounds__(256) k_logits(const float* __restrict__ W_out,
                                                const float* __restrict__ b_out,
                                                float* __restrict__ logits) {
    const int v0 = blockIdx.x * 64;
    __shared__ float Hs[16][65];           // [k][b]
    __shared__ float Ws[16][65];           // [k][v]
    const int tid = threadIdx.x;
    const int tx = tid & 15, ty = tid >> 4;
    const int lr = tid >> 2;
    const int lk4 = (tid & 3) * 4;

    float acc[4][4];
    #pragma unroll
    for (int i = 0; i < 4; i++)
        #pragma unroll
        for (int j = 0; j < 4; j++) acc[i][j] = 0.f;

    for (int kt = 0; kt < HID; kt += 16) {
        float4 hv = *(const float4*)(g_h + (size_t)lr*HID + kt + lk4);
        Hs[lk4+0][lr] = hv.x; Hs[lk4+1][lr] = hv.y;
        Hs[lk4+2][lr] = hv.z; Hs[lk4+3][lr] = hv.w;
        int v = v0 + lr;
        float4 wv = make_float4(0.f, 0.f, 0.f, 0.f);
        if (v < VOCAB) wv = *(const float4*)(W_out + (size_t)v*HID + kt + lk4);
        Ws[lk4+0][lr] = wv.x; Ws[lk4+1][lr] = wv.y;
        Ws[lk4+2][lr] = wv.z; Ws[lk4+3][lr] = wv.w;
        __syncthreads();
        #pragma unroll
        for (int kk = 0; kk < 16; kk++) {
            float a[4], bb[4];
            #pragma unroll
            for (int i = 0; i < 4; i++) a[i]  = Hs[kk][ty*4+i];
            #pragma unroll
            for (int j = 0; j < 4; j++) bb[j] = Ws[kk][tx*4+j];
            #pragma unroll
            for (int i = 0; i < 4; i++)
                #pragma unroll
                for (int j = 0; j < 4; j++) acc[i][j] = fmaf(a[i], bb[j], acc[i][j]);
        }
        __syncthreads();
    }
    #pragma unroll
    for (int i = 0; i < 4; i++) {
        int bb = ty*4 + i;
        #pragma unroll
        for (int j = 0; j < 4; j++) {
            int v = v0 + tx*4 + j;
            if (v < VOCAB)
                logits[(size_t)bb*VOCAB + v] = acc[i][j] + b_out[v];
        }
    }
}

// ---------------- kernel 6: per-row logsumexp ------------------------------
__global__ void __launch_bounds__(256) k_lse(const float* __restrict__ logits) {
    int b = blockIdx.x, tid = threadIdx.x;
    __shared__ float red[256];
    const float* row = logits + (size_t)b*VOCAB;
    float m = -1e30f;
    for (int v = tid; v < VOCAB; v += 256) m = fmaxf(m, row[v]);
    red[tid] = m; __syncthreads();
    for (int s = 128; s; s >>= 1) { if (tid < s) red[tid] = fmaxf(red[tid], red[tid+s]); __syncthreads(); }
    m = red[0]; __syncthreads();
    float sum = 0.f;
    for (int v = tid; v < VOCAB; v += 256) sum += expf(row[v] - m);
    red[tid] = sum; __syncthreads();
    for (int s = 128; s; s >>= 1) { if (tid < s) red[tid] += red[tid+s]; __syncthreads(); }
    if (tid == 0) g_lse[b] = m + logf(red[0]);
}

// ---------------- kernel 7: logp = logits - lse ----------------------------
__global__ void __launch_bounds__(256) k_sub(float* __restrict__ logp) {
    int v = blockIdx.x * 256 + threadIdx.x;
    int b = blockIdx.y;
    if (v < VOCAB) logp[(size_t)b*VOCAB + v] -= g_lse[b];
}

// ---------------- launcher -------------------------------------------------
extern "C" void kernel_launch(void* const* d_in, const int* in_sizes, int n_in,
                              void* d_out, int out_size) {
    const int*   ids    = (const int*)d_in[0];
    const float* hidden = (const float*)d_in[1];
    const float* ann    = (const float*)d_in[2];
    const float* emb    = (const float*)d_in[3];
    const float* Wk     = (const float*)d_in[4];
    const float* Wq     = (const float*)d_in[5];
    const float* bk     = (const float*)d_in[6];
    const float* v_attn = (const float*)d_in[7];
    const float* W_ih   = (const float*)d_in[8];
    const float* W_hh   = (const float*)d_in[9];
    const float* b_ih   = (const float*)d_in[10];
    const float* b_hh   = (const float*)d_in[11];
    const float* W_out  = (const float*)d_in[12];
    const float* b_out  = (const float*)d_in[13];

    float* out   = (float*)d_out;
    float* logp  = out;            // (1,B,VOCAB)
    float* o_out = out + O_OFF;    // (1,B,HID)
    float* a_out = out + A_OFF;    // (B,NK)

    k_qw    <<<dim3(HID/256, B), 256>>>(hidden, Wq, bk);
    k_feat  <<<(B*NK)/64, 256>>>(ann, Wk, v_attn);
    k_attn  <<<B, 256>>>(ann, ids, emb, a_out);
    k_gru   <<<HID, 256>>>(hidden, W_ih, W_hh, b_ih, b_hh, o_out);
    k_logits<<<(VOCAB + 63)/64, 256>>>(W_out, b_out, logp);
    k_lse   <<<B, 256>>>(logp);
    k_sub   <<<dim3((VOCAB + 255)/256, B), 256>>>(logp);
}

// round 2
// speedup vs baseline: 1.3496x; 1.3496x over previous
#include <cuda_runtime.h>
#include <math.h>

#define B 64
#define NK 2048
#define HID 1024
#define EMB 512
#define KEY 512
#define VOCAB 50257

#define O_OFF (B*VOCAB)
#define A_OFF (O_OFF + B*HID)

// ---------------- scratch ---------------------------------------------------
__device__ float g_qw[B*HID];
__device__ float g_scores[B*NK];
__device__ float g_x[B*(EMB+KEY)];
__device__ float g_h[B*HID];
__device__ float g_gi[B*3*HID];
__device__ float g_gh[B*3*HID];
__device__ float g_lse[B];

__device__ __forceinline__ float to_tf32(float x) {
    unsigned r;
    asm("cvt.rna.tf32.f32 %0, %1;" : "=r"(r) : "f"(x));
    return __uint_as_float(r);
}

// ---------------- kernel 1: qw = Q @ Wq + bk -------------------------------
__global__ void __launch_bounds__(256) k_qw(const float* __restrict__ hidden,
                                            const float* __restrict__ Wq,
                                            const float* __restrict__ bk) {
    int h = blockIdx.x * 256 + threadIdx.x;
    int b = blockIdx.y;
    __shared__ float q_s[HID];
    for (int i = threadIdx.x; i < HID; i += 256) q_s[i] = hidden[b*HID + i];
    __syncthreads();
    float acc = bk[h];
    #pragma unroll 8
    for (int k = 0; k < HID; k++)
        acc = fmaf(q_s[k], Wq[(size_t)k*HID + h], acc);
    g_qw[b*HID + h] = acc;
}

// ---------------- kernel 2: feat GEMM on tensor cores (tf32 mma.sync) ------
// scores[b,n] = sum_h v[h] * tanh( sum_k ann[b,n,k]*Wk[k,h] + qw[b,h] )
// Per block: 64 rows (A-stationary in smem), loop 8 col-chunks of 128.
// 8 warps: wm in {0,1} x 32 rows, wn in {0..3} x 32 cols.
#define AS_LD 516
#define BS_LD 132
#define FEAT_SMEM_FLOATS (64*AS_LD + 64*BS_LD + HID + HID + 64)

__global__ void __launch_bounds__(256) k_feat_tc(const float* __restrict__ ann,
                                                 const float* __restrict__ Wk,
                                                 const float* __restrict__ v_attn) {
    extern __shared__ float sm[];
    float* A_s  = sm;                       // 64 x 516
    float* B_s  = A_s + 64*AS_LD;           // 64 x 132
    float* qw_s = B_s + 64*BS_LD;           // 1024
    float* v_s  = qw_s + HID;               // 1024
    float* sc_s = v_s + HID;                // 64

    const int tile = blockIdx.x;
    const int b    = tile >> 5;
    const int row0 = (tile & 31) * 64;
    const float* A = ann + ((size_t)b * NK + row0) * KEY;  // 64 full rows, contiguous

    const int tid  = threadIdx.x;
    const int lane = tid & 31;
    const int warp = tid >> 5;
    const int wm   = warp >> 2;       // 0..1
    const int wn   = warp & 3;        // 0..3
    const int g    = lane >> 2;       // 0..7
    const int qt   = lane & 3;        // 0..3

    for (int i = tid; i < HID; i += 256) {
        qw_s[i] = g_qw[b*HID + i];
        v_s[i]  = v_attn[i];
    }
    if (tid < 64) sc_s[tid] = 0.f;

    // load A tile (contiguous 64*512 floats), convert to tf32
    {
        const float4* src = (const float4*)A;
        for (int i = tid; i < 64*128; i += 256) {
            float4 v4 = src[i];
            v4.x = to_tf32(v4.x); v4.y = to_tf32(v4.y);
            v4.z = to_tf32(v4.z); v4.w = to_tf32(v4.w);
            int r = i >> 7;
            int c = (i & 127) << 2;
            *(float4*)(A_s + r*AS_LD + c) = v4;
        }
    }

    float rs[2][2] = {{0.f,0.f},{0.f,0.f}};   // [mt][upper-half]

    for (int ncc = 0; ncc < 8; ncc++) {
        float acc[2][4][4];
        #pragma unroll
        for (int mt = 0; mt < 2; mt++)
            #pragma unroll
            for (int nt = 0; nt < 4; nt++)
                #pragma unroll
                for (int i = 0; i < 4; i++) acc[mt][nt][i] = 0.f;

        for (int kc = 0; kc < 8; kc++) {
            __syncthreads();
            // load B chunk: 64 k-rows x 128 n-cols
            {
                int kr = tid >> 2;
                int c0 = (tid & 3) * 32;
                const float* src = Wk + (size_t)(kc*64 + kr)*HID + ncc*128 + c0;
                float* dst = B_s + kr*BS_LD + c0;
                #pragma unroll
                for (int u = 0; u < 8; u++) {
                    float4 v4 = *(const float4*)(src + u*4);
                    v4.x = to_tf32(v4.x); v4.y = to_tf32(v4.y);
                    v4.z = to_tf32(v4.z); v4.w = to_tf32(v4.w);
                    *(float4*)(dst + u*4) = v4;
                }
            }
            __syncthreads();

            #pragma unroll
            for (int kk = 0; kk < 8; kk++) {
                const int kA = kc*64 + kk*8 + qt;
                unsigned a[2][4];
                #pragma unroll
                for (int mt = 0; mt < 2; mt++) {
                    int r = wm*32 + mt*16 + g;
                    a[mt][0] = __float_as_uint(A_s[r*AS_LD + kA]);
                    a[mt][1] = __float_as_uint(A_s[(r+8)*AS_LD + kA]);
                    a[mt][2] = __float_as_uint(A_s[r*AS_LD + kA + 4]);
                    a[mt][3] = __float_as_uint(A_s[(r+8)*AS_LD + kA + 4]);
                }
                #pragma unroll
                for (int nt = 0; nt < 4; nt++) {
                    int cn = wn*32 + nt*8 + g;
                    unsigned b0 = __float_as_uint(B_s[(kk*8 + qt)*BS_LD + cn]);
                    unsigned b1 = __float_as_uint(B_s[(kk*8 + qt + 4)*BS_LD + cn]);
                    #pragma unroll
                    for (int mt = 0; mt < 2; mt++) {
                        asm volatile(
                            "mma.sync.aligned.m16n8k8.row.col.f32.tf32.tf32.f32 "
                            "{%0,%1,%2,%3}, {%4,%5,%6,%7}, {%8,%9}, {%0,%1,%2,%3};"
                            : "+f"(acc[mt][nt][0]), "+f"(acc[mt][nt][1]),
                              "+f"(acc[mt][nt][2]), "+f"(acc[mt][nt][3])
                            : "r"(a[mt][0]), "r"(a[mt][1]), "r"(a[mt][2]), "r"(a[mt][3]),
                              "r"(b0), "r"(b1));
                    }
                }
            }
        }

        // fused epilogue: tanh + v-dot, accumulate per-row partials in regs
        #pragma unroll
        for (int mt = 0; mt < 2; mt++)
            #pragma unroll
            for (int up = 0; up < 2; up++) {
                float p = 0.f;
                #pragma unroll
                for (int nt = 0; nt < 4; nt++)
                    #pragma unroll
                    for (int c = 0; c < 2; c++) {
                        int h = ncc*128 + wn*32 + nt*8 + qt*2 + c;
                        float f = tanhf(acc[mt][nt][up*2 + c] + qw_s[h]);
                        p = fmaf(v_s[h], f, p);
                    }
                rs[mt][up] += p;
            }
    }

    // reduce across quad lanes (cols), then across wn warps via shared atomics
    #pragma unroll
    for (int mt = 0; mt < 2; mt++)
        #pragma unroll
        for (int up = 0; up < 2; up++) {
            float p = rs[mt][up];
            p += __shfl_xor_sync(0xffffffffu, p, 1);
            p += __shfl_xor_sync(0xffffffffu, p, 2);
            if (qt == 0)
                atomicAdd(&sc_s[wm*32 + mt*16 + up*8 + g], p);
        }
    __syncthreads();
    if (tid < 64) g_scores[(size_t)b*NK + row0 + tid] = sc_s[tid];
}

// ---------------- kernel 3: softmax + context + build x --------------------
__global__ void __launch_bounds__(256) k_attn(const float* __restrict__ ann,
                                              const int* __restrict__ ids,
                                              const float* __restrict__ emb_table,
                                              float* __restrict__ a_out) {
    int b = blockIdx.x;
    int tid = threadIdx.x;
    __shared__ float sc[NK];
    __shared__ float red[256];

    float m = -1e30f;
    for (int i = tid; i < NK; i += 256) {
        float v = g_scores[b*NK + i];
        sc[i] = v;
        m = fmaxf(m, v);
    }
    red[tid] = m; __syncthreads();
    for (int s = 128; s; s >>= 1) { if (tid < s) red[tid] = fmaxf(red[tid], red[tid+s]); __syncthreads(); }
    m = red[0]; __syncthreads();

    float sum = 0.f;
    for (int i = tid; i < NK; i += 256) { float e = expf(sc[i] - m); sc[i] = e; sum += e; }
    red[tid] = sum; __syncthreads();
    for (int s = 128; s; s >>= 1) { if (tid < s) red[tid] += red[tid+s]; __syncthreads(); }
    float inv = 1.f / red[0];
    __syncthreads();

    for (int i = tid; i < NK; i += 256) { sc[i] *= inv; a_out[(size_t)b*NK + i] = sc[i]; }
    __syncthreads();

    const float* ab = ann + (size_t)b * NK * KEY;
    int k0 = tid, k1 = tid + 256;
    float acc0 = 0.f, acc1 = 0.f;
    for (int n = 0; n < NK; n++) {
        float an = sc[n];
        acc0 = fmaf(an, ab[(size_t)n*KEY + k0], acc0);
        acc1 = fmaf(an, ab[(size_t)n*KEY + k1], acc1);
    }
    g_x[b*(EMB+KEY) + EMB + k0] = acc0;
    g_x[b*(EMB+KEY) + EMB + k1] = acc1;

    int id = ids[b];
    for (int k = tid; k < EMB; k += 256)
        g_x[b*(EMB+KEY) + k] = emb_table[(size_t)id*EMB + k];
}

// ---------------- kernel 4: 64xN GEMM, C = A[64,1024] @ W[N,1024]^T --------
__global__ void __launch_bounds__(256) k_gemm64(const float* __restrict__ Amat,
                                                const float* __restrict__ W,
                                                float* __restrict__ C, int N) {
    const int v0 = blockIdx.x * 64;
    __shared__ float Hs[16][65];
    __shared__ float Ws[16][65];
    const int tid = threadIdx.x;
    const int tx = tid & 15, ty = tid >> 4;
    const int lr = tid >> 2;
    const int lk4 = (tid & 3) * 4;

    float acc[4][4];
    #pragma unroll
    for (int i = 0; i < 4; i++)
        #pragma unroll
        for (int j = 0; j < 4; j++) acc[i][j] = 0.f;

    for (int kt = 0; kt < HID; kt += 16) {
        float4 hv = *(const float4*)(Amat + (size_t)lr*HID + kt + lk4);
        Hs[lk4+0][lr] = hv.x; Hs[lk4+1][lr] = hv.y;
        Hs[lk4+2][lr] = hv.z; Hs[lk4+3][lr] = hv.w;
        float4 wv = *(const float4*)(W + (size_t)(v0+lr)*HID + kt + lk4);
        Ws[lk4+0][lr] = wv.x; Ws[lk4+1][lr] = wv.y;
        Ws[lk4+2][lr] = wv.z; Ws[lk4+3][lr] = wv.w;
        __syncthreads();
        #pragma unroll
        for (int kk = 0; kk < 16; kk++) {
            float a[4], bb[4];
            #pragma unroll
            for (int i = 0; i < 4; i++) a[i]  = Hs[kk][ty*4+i];
            #pragma unroll
            for (int j = 0; j < 4; j++) bb[j] = Ws[kk][tx*4+j];
            #pragma unroll
            for (int i = 0; i < 4; i++)
                #pragma unroll
                for (int j = 0; j < 4; j++) acc[i][j] = fmaf(a[i], bb[j], acc[i][j]);
        }
        __syncthreads();
    }
    #pragma unroll
    for (int i = 0; i < 4; i++) {
        int bb = ty*4 + i;
        #pragma unroll
        for (int j = 0; j < 4; j++)
            C[(size_t)bb*N + v0 + tx*4 + j] = acc[i][j];
    }
}

// ---------------- kernel 5: GRU gates --------------------------------------
__global__ void __launch_bounds__(256) k_gates(const float* __restrict__ hidden,
                                               const float* __restrict__ b_ih,
                                               const float* __restrict__ b_hh,
                                               float* __restrict__ o_out) {
    int j = blockIdx.x * 256 + threadIdx.x;
    int b = blockIdx.y;
    float ir  = g_gi[b*3*HID + j]         + b_ih[j];
    float iz  = g_gi[b*3*HID + HID + j]   + b_ih[HID + j];
    float inn = g_gi[b*3*HID + 2*HID + j] + b_ih[2*HID + j];
    float hr  = g_gh[b*3*HID + j]         + b_hh[j];
    float hz  = g_gh[b*3*HID + HID + j]   + b_hh[HID + j];
    float hn  = g_gh[b*3*HID + 2*HID + j] + b_hh[2*HID + j];
    float r = 1.f / (1.f + expf(-(ir + hr)));
    float z = 1.f / (1.f + expf(-(iz + hz)));
    float n = tanhf(inn + r * hn);
    float q = hidden[b*HID + j];
    float h = (1.f - z) * n + z * q;
    g_h[b*HID + j]   = h;
    o_out[b*HID + j] = h;
}

// ---------------- kernel 6: logits GEMM (64 x VOCAB, K=1024) ---------------
__global__ void __launch_bounds__(256) k_logits(const float* __restrict__ W_out,
                                                const float* __restrict__ b_out,
                                                float* __restrict__ logits) {
    const int v0 = blockIdx.x * 64;
    __shared__ float Hs[16][65];
    __shared__ float Ws[16][65];
    const int tid = threadIdx.x;
    const int tx = tid & 15, ty = tid >> 4;
    const int lr = tid >> 2;
    const int lk4 = (tid & 3) * 4;

    float acc[4][4];
    #pragma unroll
    for (int i = 0; i < 4; i++)
        #pragma unroll
        for (int j = 0; j < 4; j++) acc[i][j] = 0.f;

    for (int kt = 0; kt < HID; kt += 16) {
        float4 hv = *(const float4*)(g_h + (size_t)lr*HID + kt + lk4);
        Hs[lk4+0][lr] = hv.x; Hs[lk4+1][lr] = hv.y;
        Hs[lk4+2][lr] = hv.z; Hs[lk4+3][lr] = hv.w;
        int v = v0 + lr;
        float4 wv = make_float4(0.f, 0.f, 0.f, 0.f);
        if (v < VOCAB) wv = *(const float4*)(W_out + (size_t)v*HID + kt + lk4);
        Ws[lk4+0][lr] = wv.x; Ws[lk4+1][lr] = wv.y;
        Ws[lk4+2][lr] = wv.z; Ws[lk4+3][lr] = wv.w;
        __syncthreads();
        #pragma unroll
        for (int kk = 0; kk < 16; kk++) {
            float a[4], bb[4];
            #pragma unroll
            for (int i = 0; i < 4; i++) a[i]  = Hs[kk][ty*4+i];
            #pragma unroll
            for (int j = 0; j < 4; j++) bb[j] = Ws[kk][tx*4+j];
            #pragma unroll
            for (int i = 0; i < 4; i++)
                #pragma unroll
                for (int j = 0; j < 4; j++) acc[i][j] = fmaf(a[i], bb[j], acc[i][j]);
        }
        __syncthreads();
    }
    #pragma unroll
    for (int i = 0; i < 4; i++) {
        int bb = ty*4 + i;
        #pragma unroll
        for (int j = 0; j < 4; j++) {
            int v = v0 + tx*4 + j;
            if (v < VOCAB)
                logits[(size_t)bb*VOCAB + v] = acc[i][j] + b_out[v];
        }
    }
}

// ---------------- kernel 7: per-row logsumexp ------------------------------
__global__ void __launch_bounds__(256) k_lse(const float* __restrict__ logits) {
    int b = blockIdx.x, tid = threadIdx.x;
    __shared__ float red[256];
    const float* row = logits + (size_t)b*VOCAB;
    float m = -1e30f;
    for (int v = tid; v < VOCAB; v += 256) m = fmaxf(m, row[v]);
    red[tid] = m; __syncthreads();
    for (int s = 128; s; s >>= 1) { if (tid < s) red[tid] = fmaxf(red[tid], red[tid+s]); __syncthreads(); }
    m = red[0]; __syncthreads();
    float sum = 0.f;
    for (int v = tid; v < VOCAB; v += 256) sum += expf(row[v] - m);
    red[tid] = sum; __syncthreads();
    for (int s = 128; s; s >>= 1) { if (tid < s) red[tid] += red[tid+s]; __syncthreads(); }
    if (tid == 0) g_lse[b] = m + logf(red[0]);
}

// ---------------- kernel 8: logp = logits - lse ----------------------------
__global__ void __launch_bounds__(256) k_sub(float* __restrict__ logp) {
    int v = blockIdx.x * 256 + threadIdx.x;
    int b = blockIdx.y;
    if (v < VOCAB) logp[(size_t)b*VOCAB + v] -= g_lse[b];
}

// ---------------- launcher -------------------------------------------------
extern "C" void kernel_launch(void* const* d_in, const int* in_sizes, int n_in,
                              void* d_out, int out_size) {
    const int*   ids    = (const int*)d_in[0];
    const float* hidden = (const float*)d_in[1];
    const float* ann    = (const float*)d_in[2];
    const float* emb    = (const float*)d_in[3];
    const float* Wk     = (const float*)d_in[4];
    const float* Wq     = (const float*)d_in[5];
    const float* bk     = (const float*)d_in[6];
    const float* v_attn = (const float*)d_in[7];
    const float* W_ih   = (const float*)d_in[8];
    const float* W_hh   = (const float*)d_in[9];
    const float* b_ih   = (const float*)d_in[10];
    const float* b_hh   = (const float*)d_in[11];
    const float* W_out  = (const float*)d_in[12];
    const float* b_out  = (const float*)d_in[13];

    float* out   = (float*)d_out;
    float* logp  = out;
    float* o_out = out + O_OFF;
    float* a_out = out + A_OFF;

    const int feat_smem = FEAT_SMEM_FLOATS * 4;
    cudaFuncSetAttribute(k_feat_tc, cudaFuncAttributeMaxDynamicSharedMemorySize, feat_smem);

    float* gi_ptr; cudaGetSymbolAddress((void**)&gi_ptr, g_gi);
    float* gh_ptr; cudaGetSymbolAddress((void**)&gh_ptr, g_gh);
    float* gx_ptr; cudaGetSymbolAddress((void**)&gx_ptr, g_x);

    k_qw     <<<dim3(HID/256, B), 256>>>(hidden, Wq, bk);
    k_feat_tc<<<(B*NK)/64, 256, feat_smem>>>(ann, Wk, v_attn);
    k_attn   <<<B, 256>>>(ann, ids, emb, a_out);
    k_gemm64 <<<3*HID/64, 256>>>(gx_ptr, W_ih, gi_ptr, 3*HID);
    k_gemm64 <<<3*HID/64, 256>>>(hidden, W_hh, gh_ptr, 3*HID);
    k_gates  <<<dim3(HID/256, B), 256>>>(hidden, b_ih, b_hh, o_out);
    k_logits <<<(VOCAB + 63)/64, 256>>>(W_out, b_out, logp);
    k_lse    <<<B, 256>>>(logp);
    k_sub    <<<dim3((VOCAB + 255)/256, B), 256>>>(logp);
}

// round 4
// speedup vs baseline: 2.1651x; 1.6042x over previous
#include <cuda_runtime.h>
#include <math.h>
#include <stdint.h>

#define B 64
#define NK 2048
#define HID 1024
#define EMB 512
#define KEY 512
#define VOCAB 50257

#define O_OFF (B*VOCAB)
#define A_OFF (O_OFF + B*HID)

// ---------------- scratch ---------------------------------------------------
__device__ float g_qw[B*HID];
__device__ float g_scores[B*NK];
__device__ float g_x[B*(EMB+KEY)];
__device__ float g_h[B*HID];
__device__ float g_gi[B*3*HID];
__device__ float g_gh[B*3*HID];
__device__ float g_lse[B];
__device__ float g_wkR[KEY*HID];      // Wk tf32-rounded, same [k][n] layout

__device__ __forceinline__ float to_tf32(float x) {
    unsigned r;
    asm("cvt.rna.tf32.f32 %0, %1;" : "=r"(r) : "f"(x));
    return __uint_as_float(r);
}
__device__ __forceinline__ uint32_t smem_u32(const void* p) {
    uint32_t a;
    asm("{ .reg .u64 t; cvta.to.shared.u64 t, %1; cvt.u32.u64 %0, t; }" : "=r"(a) : "l"(p));
    return a;
}

// ---------------- kernel 0: round Wk to tf32 -------------------------------
__global__ void __launch_bounds__(256) k_wkr(const float* __restrict__ Wk) {
    int i = blockIdx.x * 256 + threadIdx.x;
    g_wkR[i] = to_tf32(Wk[i]);
}

// ---------------- kernel 1: qw = Q @ Wq + bk -------------------------------
__global__ void __launch_bounds__(256) k_qw(const float* __restrict__ hidden,
                                            const float* __restrict__ Wq,
                                            const float* __restrict__ bk) {
    int h = blockIdx.x * 256 + threadIdx.x;
    int b = blockIdx.y;
    __shared__ float q_s[HID];
    for (int i = threadIdx.x; i < HID; i += 256) q_s[i] = hidden[b*HID + i];
    __syncthreads();
    float acc = bk[h];
    #pragma unroll 8
    for (int k = 0; k < HID; k++)
        acc = fmaf(q_s[k], Wq[(size_t)k*HID + h], acc);
    g_qw[b*HID + h] = acc;
}

// ---------------- kernel 2: feat GEMM, tf32 mma.sync + cp.async pipeline ---
// scores[b,n] = sum_h v[h] * tanh( sum_k ann[b,n,k]*Wk[k,h] + qw[b,h] )
// Block: 64 rows A-stationary (tf32 in smem). 128 chunk iterations:
// ncc = it>>3 (64-col chunk of HID), kc = it&7 (64-k chunk of KEY).
// B chunks cp.async 4-stage pipelined. 8 warps: wm(2) x 32 rows, wn(4) x 16 cols.
#define AS_LD 516
#define NSTG 4
#define BLD 68
#define B_STG (64*BLD*4)                 // 17408 bytes
#define F_A   0
#define F_B   (64*AS_LD*4)               // 132096
#define F_QW  (F_B + NSTG*B_STG)         // 201728
#define F_V   (F_QW + HID*4)
#define F_SC  (F_V + HID*4)
#define FEAT_SMEM (F_SC + 64*4)          // 210176

__global__ void __launch_bounds__(256) k_feat3(const float* __restrict__ ann,
                                               const float* __restrict__ v_attn) {
    extern __shared__ char sm[];
    const uint32_t smb = smem_u32(sm);
    float* A_s  = (float*)(sm + F_A);
    float* qw_s = (float*)(sm + F_QW);
    float* v_s  = (float*)(sm + F_V);
    float* sc_s = (float*)(sm + F_SC);

    const int bx   = blockIdx.x;
    const int b    = bx >> 5;
    const int row0 = (bx & 31) * 64;
    const int tid  = threadIdx.x;
    const int lane = tid & 31;
    const int warp = tid >> 5;
    const int wm   = warp >> 2;       // 0..1  (32-row half)
    const int wn   = warp & 3;        // 0..3  (16-col slice)
    const int g    = lane >> 2;       // 0..7
    const int qt   = lane & 3;        // 0..3

    for (int i = tid; i < HID; i += 256) {
        qw_s[i] = g_qw[b*HID + i];
        v_s[i]  = v_attn[i];
    }
    if (tid < 64) sc_s[tid] = 0.f;

    // A tile load (once): 64 rows x 512 k, tf32-rounded
    {
        const float4* src = (const float4*)(ann + ((size_t)b * NK + row0) * KEY);
        for (int i = tid; i < 64*128; i += 256) {
            float4 v4 = src[i];
            v4.x = to_tf32(v4.x); v4.y = to_tf32(v4.y);
            v4.z = to_tf32(v4.z); v4.w = to_tf32(v4.w);
            int r = i >> 7;
            int c = (i & 127) << 2;
            *(float4*)(A_s + r*AS_LD + c) = v4;
        }
    }

    // cp.async stage issue: chunk it -> (ncc, kc), buffer it&3
    auto issue = [&](int it) {
        int ncc = it >> 3, kc = it & 7, buf = it & 3;
        const float* src = g_wkR + (size_t)(kc*64)*HID + ncc*64;
        #pragma unroll
        for (int u = 0; u < 4; u++) {
            int gi = tid + u*256;
            int r = gi >> 4, c4 = gi & 15;
            uint32_t dst = smb + F_B + buf*B_STG + (uint32_t)(r*BLD + c4*4)*4;
            const float* s = src + (size_t)r*HID + c4*4;
            asm volatile("cp.async.cg.shared.global [%0], [%1], 16;" :: "r"(dst), "l"(s));
        }
        asm volatile("cp.async.commit_group;" ::: "memory");
    };

    issue(0); issue(1); issue(2);

    float rs[2][2] = {{0.f,0.f},{0.f,0.f}};
    float acc[2][2][4];

    for (int it = 0; it < 128; it++) {
        const int buf = it & 3;
        const int kc  = it & 7;
        asm volatile("cp.async.wait_group 2;" ::: "memory");
        __syncthreads();

        if (kc == 0) {
            #pragma unroll
            for (int mt = 0; mt < 2; mt++)
                #pragma unroll
                for (int nt = 0; nt < 2; nt++)
                    #pragma unroll
                    for (int i = 0; i < 4; i++) acc[mt][nt][i] = 0.f;
        }

        const float* Bst = (const float*)(sm + F_B + buf*B_STG);
        const int kA = kc * 64;
        #pragma unroll
        for (int kk = 0; kk < 8; kk++) {
            const int ka = kA + kk*8 + qt;
            unsigned a[2][4];
            #pragma unroll
            for (int mt = 0; mt < 2; mt++) {
                int r = wm*32 + mt*16 + g;
                a[mt][0] = __float_as_uint(A_s[r*AS_LD + ka]);
                a[mt][1] = __float_as_uint(A_s[(r+8)*AS_LD + ka]);
                a[mt][2] = __float_as_uint(A_s[r*AS_LD + ka + 4]);
                a[mt][3] = __float_as_uint(A_s[(r+8)*AS_LD + ka + 4]);
            }
            #pragma unroll
            for (int nt = 0; nt < 2; nt++) {
                int cn = wn*16 + nt*8 + g;
                unsigned b0 = __float_as_uint(Bst[(kk*8 + qt)*BLD + cn]);
                unsigned b1 = __float_as_uint(Bst[(kk*8 + qt + 4)*BLD + cn]);
                #pragma unroll
                for (int mt = 0; mt < 2; mt++) {
                    asm volatile(
                        "mma.sync.aligned.m16n8k8.row.col.f32.tf32.tf32.f32 "
                        "{%0,%1,%2,%3}, {%4,%5,%6,%7}, {%8,%9}, {%0,%1,%2,%3};"
                        : "+f"(acc[mt][nt][0]), "+f"(acc[mt][nt][1]),
                          "+f"(acc[mt][nt][2]), "+f"(acc[mt][nt][3])
                        : "r"(a[mt][0]), "r"(a[mt][1]), "r"(a[mt][2]), "r"(a[mt][3]),
                          "r"(b0), "r"(b1));
                }
            }
        }

        if (kc == 7) {
            // full K done for this 64-col chunk: tanh + v-dot into register partials
            const int ncc = it >> 3;
            #pragma unroll
            for (int mt = 0; mt < 2; mt++)
                #pragma unroll
                for (int nt = 0; nt < 2; nt++) {
                    int h0 = ncc*64 + wn*16 + nt*8 + qt*2;
                    float v0 = v_s[h0],      q0u = qw_s[h0];
                    float v1 = v_s[h0 + 1],  q1u = qw_s[h0 + 1];
                    rs[mt][0] = fmaf(v0, tanhf(acc[mt][nt][0] + q0u), rs[mt][0]);
                    rs[mt][0] = fmaf(v1, tanhf(acc[mt][nt][1] + q1u), rs[mt][0]);
                    rs[mt][1] = fmaf(v0, tanhf(acc[mt][nt][2] + q0u), rs[mt][1]);
                    rs[mt][1] = fmaf(v1, tanhf(acc[mt][nt][3] + q1u), rs[mt][1]);
                }
        }

        if (it + 3 < 128) issue(it + 3);
    }

    // reduce across quad (qt) lanes, then across wn warps via shared atomics
    #pragma unroll
    for (int mt = 0; mt < 2; mt++)
        #pragma unroll
        for (int up = 0; up < 2; up++) {
            float p = rs[mt][up];
            p += __shfl_xor_sync(0xffffffffu, p, 1);
            p += __shfl_xor_sync(0xffffffffu, p, 2);
            if (qt == 0)
                atomicAdd(&sc_s[wm*32 + mt*16 + up*8 + g], p);
        }
    __syncthreads();
    if (tid < 64) g_scores[(size_t)b*NK + row0 + tid] = sc_s[tid];
}

// ---------------- kernel 3: softmax + emb copy -----------------------------
__global__ void __launch_bounds__(256) k_attn_sm(const int* __restrict__ ids,
                                                 const float* __restrict__ emb_table,
                                                 float* __restrict__ a_out) {
    int b = blockIdx.x;
    int tid = threadIdx.x;
    __shared__ float sc[NK];
    __shared__ float red[256];

    float m = -1e30f;
    for (int i = tid; i < NK; i += 256) {
        float v = g_scores[b*NK + i];
        sc[i] = v;
        m = fmaxf(m, v);
    }
    red[tid] = m; __syncthreads();
    for (int s = 128; s; s >>= 1) { if (tid < s) red[tid] = fmaxf(red[tid], red[tid+s]); __syncthreads(); }
    m = red[0]; __syncthreads();

    float sum = 0.f;
    for (int i = tid; i < NK; i += 256) { float e = expf(sc[i] - m); sc[i] = e; sum += e; }
    red[tid] = sum; __syncthreads();
    for (int s = 128; s; s >>= 1) { if (tid < s) red[tid] += red[tid+s]; __syncthreads(); }
    float inv = 1.f / red[0];
    __syncthreads();

    for (int i = tid; i < NK; i += 256)
        a_out[(size_t)b*NK + i] = sc[i] * inv;

    int id = ids[b];
    for (int k = tid; k < EMB; k += 256)
        g_x[b*(EMB+KEY) + k] = emb_table[(size_t)id*EMB + k];
}

// ---------------- kernel 4: context = a . ann ------------------------------
// grid (B, 8): block covers 64 k-columns; 256 thr = 4 row-groups x 64 cols.
__global__ void __launch_bounds__(256) k_ctx(const float* __restrict__ ann,
                                             const float* __restrict__ a_out) {
    int b = blockIdx.x;
    int p = blockIdx.y;
    int tid = threadIdx.x;
    int c  = tid & 63;
    int rg = tid >> 6;
    __shared__ float part[4][64];

    const float* ab = ann + (size_t)b*NK*KEY + p*64 + c;
    const float* av = a_out + (size_t)b*NK;
    float acc = 0.f;
    for (int n = rg; n < NK; n += 4)
        acc = fmaf(av[n], ab[(size_t)n*KEY], acc);
    part[rg][c] = acc;
    __syncthreads();
    if (rg == 0)
        g_x[b*(EMB+KEY) + EMB + p*64 + c] =
            part[0][c] + part[1][c] + part[2][c] + part[3][c];
}

// ---------------- kernel 5: gi/gh GEMMs merged -----------------------------
__global__ void __launch_bounds__(256) k_gemm2(const float* __restrict__ hidden,
                                               const float* __restrict__ W_ih,
                                               const float* __restrict__ W_hh) {
    const float* Amat = blockIdx.y ? hidden : g_x;
    const float* W    = blockIdx.y ? W_hh   : W_ih;
    float*       C    = blockIdx.y ? g_gh   : g_gi;
    const int v0 = blockIdx.x * 64;
    __shared__ float Hs[16][65];
    __shared__ float Ws[16][65];
    const int tid = threadIdx.x;
    const int tx = tid & 15, ty = tid >> 4;
    const int lr = tid >> 2;
    const int lk4 = (tid & 3) * 4;

    float acc[4][4];
    #pragma unroll
    for (int i = 0; i < 4; i++)
        #pragma unroll
        for (int j = 0; j < 4; j++) acc[i][j] = 0.f;

    for (int kt = 0; kt < HID; kt += 16) {
        float4 hv = *(const float4*)(Amat + (size_t)lr*HID + kt + lk4);
        Hs[lk4+0][lr] = hv.x; Hs[lk4+1][lr] = hv.y;
        Hs[lk4+2][lr] = hv.z; Hs[lk4+3][lr] = hv.w;
        float4 wv = *(const float4*)(W + (size_t)(v0+lr)*HID + kt + lk4);
        Ws[lk4+0][lr] = wv.x; Ws[lk4+1][lr] = wv.y;
        Ws[lk4+2][lr] = wv.z; Ws[lk4+3][lr] = wv.w;
        __syncthreads();
        #pragma unroll
        for (int kk = 0; kk < 16; kk++) {
            float a[4], bbv[4];
            #pragma unroll
            for (int i = 0; i < 4; i++) a[i]   = Hs[kk][ty*4+i];
            #pragma unroll
            for (int j = 0; j < 4; j++) bbv[j] = Ws[kk][tx*4+j];
            #pragma unroll
            for (int i = 0; i < 4; i++)
                #pragma unroll
                for (int j = 0; j < 4; j++) acc[i][j] = fmaf(a[i], bbv[j], acc[i][j]);
        }
        __syncthreads();
    }
    #pragma unroll
    for (int i = 0; i < 4; i++) {
        int bb = ty*4 + i;
        #pragma unroll
        for (int j = 0; j < 4; j++)
            C[(size_t)bb*3*HID + v0 + tx*4 + j] = acc[i][j];
    }
}

// ---------------- kernel 6: GRU gates --------------------------------------
__global__ void __launch_bounds__(256) k_gates(const float* __restrict__ hidden,
                                               const float* __restrict__ b_ih,
                                               const float* __restrict__ b_hh,
                                               float* __restrict__ o_out) {
    int j = blockIdx.x * 256 + threadIdx.x;
    int b = blockIdx.y;
    float ir  = g_gi[b*3*HID + j]         + b_ih[j];
    float iz  = g_gi[b*3*HID + HID + j]   + b_ih[HID + j];
    float inn = g_gi[b*3*HID + 2*HID + j] + b_ih[2*HID + j];
    float hr  = g_gh[b*3*HID + j]         + b_hh[j];
    float hz  = g_gh[b*3*HID + HID + j]   + b_hh[HID + j];
    float hn  = g_gh[b*3*HID + 2*HID + j] + b_hh[2*HID + j];
    float r = 1.f / (1.f + expf(-(ir + hr)));
    float z = 1.f / (1.f + expf(-(iz + hz)));
    float n = tanhf(inn + r * hn);
    float q = hidden[b*HID + j];
    float h = (1.f - z) * n + z * q;
    g_h[b*HID + j]   = h;
    o_out[b*HID + j] = h;
}

// ---------------- kernel 7: logits GEMM (SIMT, known good) -----------------
__global__ void __launch_bounds__(256) k_logits(const float* __restrict__ W_out,
                                                const float* __restrict__ b_out,
                                                float* __restrict__ logits) {
    const int v0 = blockIdx.x * 64;
    __shared__ float Hs[16][65];
    __shared__ float Ws[16][65];
    const int tid = threadIdx.x;
    const int tx = tid & 15, ty = tid >> 4;
    const int lr = tid >> 2;
    const int lk4 = (tid & 3) * 4;

    float acc[4][4];
    #pragma unroll
    for (int i = 0; i < 4; i++)
        #pragma unroll
        for (int j = 0; j < 4; j++) acc[i][j] = 0.f;

    for (int kt = 0; kt < HID; kt += 16) {
        float4 hv = *(const float4*)(g_h + (size_t)lr*HID + kt + lk4);
        Hs[lk4+0][lr] = hv.x; Hs[lk4+1][lr] = hv.y;
        Hs[lk4+2][lr] = hv.z; Hs[lk4+3][lr] = hv.w;
        int v = v0 + lr;
        float4 wv = make_float4(0.f, 0.f, 0.f, 0.f);
        if (v < VOCAB) wv = *(const float4*)(W_out + (size_t)v*HID + kt + lk4);
        Ws[lk4+0][lr] = wv.x; Ws[lk4+1][lr] = wv.y;
        Ws[lk4+2][lr] = wv.z; Ws[lk4+3][lr] = wv.w;
        __syncthreads();
        #pragma unroll
        for (int kk = 0; kk < 16; kk++) {
            float a[4], bb[4];
            #pragma unroll
            for (int i = 0; i < 4; i++) a[i]  = Hs[kk][ty*4+i];
            #pragma unroll
            for (int j = 0; j < 4; j++) bb[j] = Ws[kk][tx*4+j];
            #pragma unroll
            for (int i = 0; i < 4; i++)
                #pragma unroll
                for (int j = 0; j < 4; j++) acc[i][j] = fmaf(a[i], bb[j], acc[i][j]);
        }
        __syncthreads();
    }
    #pragma unroll
    for (int i = 0; i < 4; i++) {
        int bb = ty*4 + i;
        #pragma unroll
        for (int j = 0; j < 4; j++) {
            int v = v0 + tx*4 + j;
            if (v < VOCAB)
                logits[(size_t)bb*VOCAB + v] = acc[i][j] + b_out[v];
        }
    }
}

// ---------------- kernel 8: per-row logsumexp ------------------------------
__global__ void __launch_bounds__(256) k_lse(const float* __restrict__ logits) {
    int b = blockIdx.x, tid = threadIdx.x;
    __shared__ float red[256];
    const float* row = logits + (size_t)b*VOCAB;
    float m = -1e30f;
    for (int v = tid; v < VOCAB; v += 256) m = fmaxf(m, row[v]);
    red[tid] = m; __syncthreads();
    for (int s = 128; s; s >>= 1) { if (tid < s) red[tid] = fmaxf(red[tid], red[tid+s]); __syncthreads(); }
    m = red[0]; __syncthreads();
    float sum = 0.f;
    for (int v = tid; v < VOCAB; v += 256) sum += expf(row[v] - m);
    red[tid] = sum; __syncthreads();
    for (int s = 128; s; s >>= 1) { if (tid < s) red[tid] += red[tid+s]; __syncthreads(); }
    if (tid == 0) g_lse[b] = m + logf(red[0]);
}

// ---------------- kernel 9: logp = logits - lse ----------------------------
__global__ void __launch_bounds__(256) k_sub(float* __restrict__ logp) {
    int v = blockIdx.x * 256 + threadIdx.x;
    int b = blockIdx.y;
    if (v < VOCAB) logp[(size_t)b*VOCAB + v] -= g_lse[b];
}

// ---------------- launcher -------------------------------------------------
extern "C" void kernel_launch(void* const* d_in, const int* in_sizes, int n_in,
                              void* d_out, int out_size) {
    const int*   ids    = (const int*)d_in[0];
    const float* hidden = (const float*)d_in[1];
    const float* ann    = (const float*)d_in[2];
    const float* emb    = (const float*)d_in[3];
    const float* Wk     = (const float*)d_in[4];
    const float* Wq     = (const float*)d_in[5];
    const float* bk     = (const float*)d_in[6];
    const float* v_attn = (const float*)d_in[7];
    const float* W_ih   = (const float*)d_in[8];
    const float* W_hh   = (const float*)d_in[9];
    const float* b_ih   = (const float*)d_in[10];
    const float* b_hh   = (const float*)d_in[11];
    const float* W_out  = (const float*)d_in[12];
    const float* b_out  = (const float*)d_in[13];

    float* out   = (float*)d_out;
    float* logp  = out;
    float* o_out = out + O_OFF;
    float* a_out = out + A_OFF;

    cudaFuncSetAttribute(k_feat3, cudaFuncAttributeMaxDynamicSharedMemorySize, FEAT_SMEM);

    k_wkr    <<<(KEY*HID)/256, 256>>>(Wk);
    k_qw     <<<dim3(HID/256, B), 256>>>(hidden, Wq, bk);
    k_feat3  <<<(B*NK)/64, 256, FEAT_SMEM>>>(ann, v_attn);
    k_attn_sm<<<B, 256>>>(ids, emb, a_out);
    k_ctx    <<<dim3(B, 8), 256>>>(ann, a_out);
    k_gemm2  <<<dim3(3*HID/64, 2), 256>>>(hidden, W_ih, W_hh);
    k_gates  <<<dim3(HID/256, B), 256>>>(hidden, b_ih, b_hh, o_out);
    k_logits <<<(VOCAB + 63)/64, 256>>>(W_out, b_out, logp);
    k_lse    <<<B, 256>>>(logp);
    k_sub    <<<dim3((VOCAB + 255)/256, B), 256>>>(logp);
}

// round 5
// speedup vs baseline: 2.7678x; 1.2784x over previous
#include <cuda_runtime.h>
#include <math.h>
#include <stdint.h>

#define B 64
#define NK 2048
#define HID 1024
#define EMB 512
#define KEY 512
#define VOCAB 50257

#define O_OFF (B*VOCAB)
#define A_OFF (O_OFF + B*HID)

// ---------------- scratch ---------------------------------------------------
__device__ float g_qw[B*HID];
__device__ float g_scores[B*NK];
__device__ float g_x[B*(EMB+KEY)];
__device__ float g_h[B*HID];
__device__ float g_gi[B*3*HID];
__device__ float g_gh[B*3*HID];
__device__ float g_lse[B];
__device__ float g_wkR[KEY*HID];      // Wk tf32-rounded, [k][n] layout

__device__ __forceinline__ float to_tf32(float x) {
    unsigned r;
    asm("cvt.rna.tf32.f32 %0, %1;" : "=r"(r) : "f"(x));
    return __uint_as_float(r);
}
__device__ __forceinline__ uint32_t smem_u32(const void* p) {
    uint32_t a;
    asm("{ .reg .u64 t; cvta.to.shared.u64 t, %1; cvt.u32.u64 %0, t; }" : "=r"(a) : "l"(p));
    return a;
}

// ---------------- kernel 0: round Wk to tf32 -------------------------------
__global__ void __launch_bounds__(256) k_wkr(const float* __restrict__ Wk) {
    int i = blockIdx.x * 256 + threadIdx.x;
    g_wkR[i] = to_tf32(Wk[i]);
}

// ---------------- kernel 1: qw = Q @ Wq + bk -------------------------------
__global__ void __launch_bounds__(256) k_qw(const float* __restrict__ hidden,
                                            const float* __restrict__ Wq,
                                            const float* __restrict__ bk) {
    int h = blockIdx.x * 256 + threadIdx.x;
    int b = blockIdx.y;
    __shared__ float q_s[HID];
    for (int i = threadIdx.x; i < HID; i += 256) q_s[i] = hidden[b*HID + i];
    __syncthreads();
    float acc = bk[h];
    #pragma unroll 8
    for (int k = 0; k < HID; k++)
        acc = fmaf(q_s[k], Wq[(size_t)k*HID + h], acc);
    g_qw[b*HID + h] = acc;
}

// ---------------- kernel 2: feat GEMM, tf32 mma + cp.async -----------------
// Block: 64 rows A-stationary. 128 its: ncc = it>>4 (128-col chunk of HID),
// kc = it&15 (32-k chunk). 8 warps: wm(2) x 32 rows, wn(4) x 32 cols.
#define AS_LD 516
#define NSTG 4
#define BLD 136
#define B_STG (32*BLD*4)                 // 17408 bytes
#define F_A   0
#define F_B   (64*AS_LD*4)               // 132096
#define F_QW  (F_B + NSTG*B_STG)         // 201728
#define F_V   (F_QW + HID*4)
#define F_SC  (F_V + HID*4)
#define FEAT_SMEM (F_SC + 64*4)          // 210176

__global__ void __launch_bounds__(256) k_feat4(const float* __restrict__ ann,
                                               const float* __restrict__ v_attn) {
    extern __shared__ char sm[];
    const uint32_t smb = smem_u32(sm);
    float* A_s  = (float*)(sm + F_A);
    float* qw_s = (float*)(sm + F_QW);
    float* v_s  = (float*)(sm + F_V);
    float* sc_s = (float*)(sm + F_SC);

    const int bx   = blockIdx.x;
    const int b    = bx >> 5;
    const int row0 = (bx & 31) * 64;
    const int tid  = threadIdx.x;
    const int lane = tid & 31;
    const int warp = tid >> 5;
    const int wm   = warp >> 2;       // 0..1
    const int wn   = warp & 3;        // 0..3 (32-col slice of 128-chunk)
    const int g    = lane >> 2;       // 0..7
    const int qt   = lane & 3;        // 0..3

    for (int i = tid; i < HID; i += 256) {
        qw_s[i] = g_qw[b*HID + i];
        v_s[i]  = v_attn[i];
    }
    if (tid < 64) sc_s[tid] = 0.f;

    // A tile load (once): 64 rows x 512 k, tf32-rounded
    {
        const float4* src = (const float4*)(ann + ((size_t)b * NK + row0) * KEY);
        for (int i = tid; i < 64*128; i += 256) {
            float4 v4 = src[i];
            v4.x = to_tf32(v4.x); v4.y = to_tf32(v4.y);
            v4.z = to_tf32(v4.z); v4.w = to_tf32(v4.w);
            int r = i >> 7;
            int c = (i & 127) << 2;
            *(float4*)(A_s + r*AS_LD + c) = v4;
        }
    }

    // stage: 32 k-rows x 128 n-cols of Wk
    auto issue = [&](int it) {
        int ncc = it >> 4, kc = it & 15, buf = it & 3;
        const float* src = g_wkR + (size_t)(kc*32)*HID + ncc*128;
        #pragma unroll
        for (int u = 0; u < 4; u++) {
            int gi = tid + u*256;
            int r = gi >> 5, c4 = gi & 31;
            uint32_t dst = smb + F_B + buf*B_STG + (uint32_t)(r*BLD + c4*4)*4;
            const float* s = src + (size_t)r*HID + c4*4;
            asm volatile("cp.async.cg.shared.global [%0], [%1], 16;" :: "r"(dst), "l"(s));
        }
        asm volatile("cp.async.commit_group;" ::: "memory");
    };

    issue(0); issue(1); issue(2);

    float rs[2][2] = {{0.f,0.f},{0.f,0.f}};
    float acc[2][4][4];

    for (int it = 0; it < 128; it++) {
        const int buf = it & 3;
        const int kc  = it & 15;
        asm volatile("cp.async.wait_group 2;" ::: "memory");
        __syncthreads();

        if (kc == 0) {
            #pragma unroll
            for (int mt = 0; mt < 2; mt++)
                #pragma unroll
                for (int nt = 0; nt < 4; nt++)
                    #pragma unroll
                    for (int i = 0; i < 4; i++) acc[mt][nt][i] = 0.f;
        }

        const float* Bst = (const float*)(sm + F_B + buf*B_STG);
        #pragma unroll
        for (int kk = 0; kk < 4; kk++) {
            const int ka = kc*32 + kk*8 + qt;
            unsigned a[2][4];
            #pragma unroll
            for (int mt = 0; mt < 2; mt++) {
                int r = wm*32 + mt*16 + g;
                a[mt][0] = __float_as_uint(A_s[r*AS_LD + ka]);
                a[mt][1] = __float_as_uint(A_s[(r+8)*AS_LD + ka]);
                a[mt][2] = __float_as_uint(A_s[r*AS_LD + ka + 4]);
                a[mt][3] = __float_as_uint(A_s[(r+8)*AS_LD + ka + 4]);
            }
            #pragma unroll
            for (int nt = 0; nt < 4; nt++) {
                int cn = wn*32 + nt*8 + g;
                unsigned b0 = __float_as_uint(Bst[(kk*8 + qt)*BLD + cn]);
                unsigned b1 = __float_as_uint(Bst[(kk*8 + qt + 4)*BLD + cn]);
                #pragma unroll
                for (int mt = 0; mt < 2; mt++) {
                    asm volatile(
                        "mma.sync.aligned.m16n8k8.row.col.f32.tf32.tf32.f32 "
                        "{%0,%1,%2,%3}, {%4,%5,%6,%7}, {%8,%9}, {%0,%1,%2,%3};"
                        : "+f"(acc[mt][nt][0]), "+f"(acc[mt][nt][1]),
                          "+f"(acc[mt][nt][2]), "+f"(acc[mt][nt][3])
                        : "r"(a[mt][0]), "r"(a[mt][1]), "r"(a[mt][2]), "r"(a[mt][3]),
                          "r"(b0), "r"(b1));
                }
            }
        }

        if (kc == 15) {
            const int ncc = it >> 4;
            #pragma unroll
            for (int mt = 0; mt < 2; mt++)
                #pragma unroll
                for (int nt = 0; nt < 4; nt++) {
                    int h0 = ncc*128 + wn*32 + nt*8 + qt*2;
                    float v0 = v_s[h0],     q0u = qw_s[h0];
                    float v1 = v_s[h0 + 1], q1u = qw_s[h0 + 1];
                    rs[mt][0] = fmaf(v0, tanhf(acc[mt][nt][0] + q0u), rs[mt][0]);
                    rs[mt][0] = fmaf(v1, tanhf(acc[mt][nt][1] + q1u), rs[mt][0]);
                    rs[mt][1] = fmaf(v0, tanhf(acc[mt][nt][2] + q0u), rs[mt][1]);
                    rs[mt][1] = fmaf(v1, tanhf(acc[mt][nt][3] + q1u), rs[mt][1]);
                }
        }

        if (it + 3 < 128) issue(it + 3);
    }

    #pragma unroll
    for (int mt = 0; mt < 2; mt++)
        #pragma unroll
        for (int up = 0; up < 2; up++) {
            float p = rs[mt][up];
            p += __shfl_xor_sync(0xffffffffu, p, 1);
            p += __shfl_xor_sync(0xffffffffu, p, 2);
            if (qt == 0)
                atomicAdd(&sc_s[wm*32 + mt*16 + up*8 + g], p);
        }
    __syncthreads();
    if (tid < 64) g_scores[(size_t)b*NK + row0 + tid] = sc_s[tid];
}

// ---------------- kernel 3: softmax + emb copy -----------------------------
__global__ void __launch_bounds__(256) k_attn_sm(const int* __restrict__ ids,
                                                 const float* __restrict__ emb_table,
                                                 float* __restrict__ a_out) {
    int b = blockIdx.x;
    int tid = threadIdx.x;
    __shared__ float sc[NK];
    __shared__ float red[256];

    float m = -1e30f;
    for (int i = tid; i < NK; i += 256) {
        float v = g_scores[b*NK + i];
        sc[i] = v;
        m = fmaxf(m, v);
    }
    red[tid] = m; __syncthreads();
    for (int s = 128; s; s >>= 1) { if (tid < s) red[tid] = fmaxf(red[tid], red[tid+s]); __syncthreads(); }
    m = red[0]; __syncthreads();

    float sum = 0.f;
    for (int i = tid; i < NK; i += 256) { float e = expf(sc[i] - m); sc[i] = e; sum += e; }
    red[tid] = sum; __syncthreads();
    for (int s = 128; s; s >>= 1) { if (tid < s) red[tid] += red[tid+s]; __syncthreads(); }
    float inv = 1.f / red[0];
    __syncthreads();

    for (int i = tid; i < NK; i += 256)
        a_out[(size_t)b*NK + i] = sc[i] * inv;

    int id = ids[b];
    for (int k = tid; k < EMB; k += 256)
        g_x[b*(EMB+KEY) + k] = emb_table[(size_t)id*EMB + k];
}

// ---------------- kernel 4: context = a . ann ------------------------------
__global__ void __launch_bounds__(256) k_ctx(const float* __restrict__ ann,
                                             const float* __restrict__ a_out) {
    int b = blockIdx.x;
    int p = blockIdx.y;
    int tid = threadIdx.x;
    int c  = tid & 63;
    int rg = tid >> 6;
    __shared__ float part[4][64];

    const float* ab = ann + (size_t)b*NK*KEY + p*64 + c;
    const float* av = a_out + (size_t)b*NK;
    float acc = 0.f;
    for (int n = rg; n < NK; n += 4)
        acc = fmaf(av[n], ab[(size_t)n*KEY], acc);
    part[rg][c] = acc;
    __syncthreads();
    if (rg == 0)
        g_x[b*(EMB+KEY) + EMB + p*64 + c] =
            part[0][c] + part[1][c] + part[2][c] + part[3][c];
}

// ---------------- kernel 5: generic 64xN GEMM (SIMT) -----------------------
__global__ void __launch_bounds__(256) k_gemm64b(const float* __restrict__ Amat,
                                                 const float* __restrict__ W,
                                                 float* __restrict__ C) {
    const int v0 = blockIdx.x * 64;
    __shared__ float Hs[16][65];
    __shared__ float Ws[16][65];
    const int tid = threadIdx.x;
    const int tx = tid & 15, ty = tid >> 4;
    const int lr = tid >> 2;
    const int lk4 = (tid & 3) * 4;

    float acc[4][4];
    #pragma unroll
    for (int i = 0; i < 4; i++)
        #pragma unroll
        for (int j = 0; j < 4; j++) acc[i][j] = 0.f;

    for (int kt = 0; kt < HID; kt += 16) {
        float4 hv = *(const float4*)(Amat + (size_t)lr*HID + kt + lk4);
        Hs[lk4+0][lr] = hv.x; Hs[lk4+1][lr] = hv.y;
        Hs[lk4+2][lr] = hv.z; Hs[lk4+3][lr] = hv.w;
        float4 wv = *(const float4*)(W + (size_t)(v0+lr)*HID + kt + lk4);
        Ws[lk4+0][lr] = wv.x; Ws[lk4+1][lr] = wv.y;
        Ws[lk4+2][lr] = wv.z; Ws[lk4+3][lr] = wv.w;
        __syncthreads();
        #pragma unroll
        for (int kk = 0; kk < 16; kk++) {
            float a[4], bbv[4];
            #pragma unroll
            for (int i = 0; i < 4; i++) a[i]   = Hs[kk][ty*4+i];
            #pragma unroll
            for (int j = 0; j < 4; j++) bbv[j] = Ws[kk][tx*4+j];
            #pragma unroll
            for (int i = 0; i < 4; i++)
                #pragma unroll
                for (int j = 0; j < 4; j++) acc[i][j] = fmaf(a[i], bbv[j], acc[i][j]);
        }
        __syncthreads();
    }
    #pragma unroll
    for (int i = 0; i < 4; i++) {
        int bb = ty*4 + i;
        #pragma unroll
        for (int j = 0; j < 4; j++)
            C[(size_t)bb*3*HID + v0 + tx*4 + j] = acc[i][j];
    }
}

// ---------------- kernel 6: GRU gates --------------------------------------
__global__ void __launch_bounds__(256) k_gates(const float* __restrict__ hidden,
                                               const float* __restrict__ b_ih,
                                               const float* __restrict__ b_hh,
                                               float* __restrict__ o_out) {
    int j = blockIdx.x * 256 + threadIdx.x;
    int b = blockIdx.y;
    float ir  = g_gi[b*3*HID + j]         + b_ih[j];
    float iz  = g_gi[b*3*HID + HID + j]   + b_ih[HID + j];
    float inn = g_gi[b*3*HID + 2*HID + j] + b_ih[2*HID + j];
    float hr  = g_gh[b*3*HID + j]         + b_hh[j];
    float hz  = g_gh[b*3*HID + HID + j]   + b_hh[HID + j];
    float hn  = g_gh[b*3*HID + 2*HID + j] + b_hh[2*HID + j];
    float r = 1.f / (1.f + expf(-(ir + hr)));
    float z = 1.f / (1.f + expf(-(iz + hz)));
    float n = tanhf(inn + r * hn);
    float q = hidden[b*HID + j];
    float h = (1.f - z) * n + z * q;
    g_h[b*HID + j]   = h;
    o_out[b*HID + j] = h;
}

// ---------------- kernel 7: logits via tf32 mma + cp.async -----------------
// Block: 64 rows (all B) x 128 vocab cols, K=1024 in 16 chunks of 64.
// A = g_h [64][1024] row-major; B = W_out [v][k] = col-major KxN (native!).
#define L_ALD 68
#define L_BLD 68
#define L_ASTG (64*L_ALD*4)              // 17408
#define L_BSTG (128*L_BLD*4)             // 34816
#define L_STG  (L_ASTG + L_BSTG)         // 52224
#define LOG_SMEM (3*L_STG)               // 156672

__global__ void __launch_bounds__(256) k_logits_tc4(const float* __restrict__ W_out,
                                                    const float* __restrict__ b_out,
                                                    float* __restrict__ logits) {
    extern __shared__ char sm[];
    const uint32_t smb = smem_u32(sm);
    const int v0 = blockIdx.x * 128;
    const int tid = threadIdx.x;
    const int lane = tid & 31;
    const int warp = tid >> 5;
    const int wm = warp >> 2;         // 0..1 (32-row half)
    const int wn = warp & 3;          // 0..3 (32-col slice)
    const int g  = lane >> 2;
    const int qt = lane & 3;

    auto issue = [&](int kc) {
        int buf = kc % 3;
        // A: 64 rows x 64 k
        {
            const float* src = g_h + kc*64;
            #pragma unroll
            for (int u = 0; u < 4; u++) {
                int gi = tid + u*256;
                int r = gi >> 4, c4 = gi & 15;
                uint32_t dst = smb + buf*L_STG + (uint32_t)(r*L_ALD + c4*4)*4;
                const float* s = src + (size_t)r*HID + c4*4;
                asm volatile("cp.async.cg.shared.global [%0], [%1], 16;" :: "r"(dst), "l"(s));
            }
        }
        // B: 128 vocab-rows x 64 k (stored [n][k] in smem)
        {
            #pragma unroll
            for (int u = 0; u < 8; u++) {
                int gi = tid + u*256;
                int r = gi >> 4, c4 = gi & 15;
                int v = v0 + r;
                uint32_t dst = smb + buf*L_STG + L_ASTG + (uint32_t)(r*L_BLD + c4*4)*4;
                const float* s = (v < VOCAB)
                    ? (W_out + (size_t)v*HID + kc*64 + c4*4) : W_out;
                unsigned sz = (v < VOCAB) ? 16u : 0u;
                asm volatile("cp.async.cg.shared.global [%0], [%1], 16, %2;"
                             :: "r"(dst), "l"(s), "r"(sz));
            }
        }
        asm volatile("cp.async.commit_group;" ::: "memory");
    };

    issue(0); issue(1);

    float acc[2][4][4];
    #pragma unroll
    for (int mt = 0; mt < 2; mt++)
        #pragma unroll
        for (int nt = 0; nt < 4; nt++)
            #pragma unroll
            for (int i = 0; i < 4; i++) acc[mt][nt][i] = 0.f;

    for (int kc = 0; kc < 16; kc++) {
        const int buf = kc % 3;
        asm volatile("cp.async.wait_group 1;" ::: "memory");
        __syncthreads();

        const float* A_s = (const float*)(sm + buf*L_STG);
        const float* B_s = (const float*)(sm + buf*L_STG + L_ASTG);
        #pragma unroll
        for (int kk = 0; kk < 8; kk++) {
            const int ka = kk*8 + qt;
            unsigned a[2][4];
            #pragma unroll
            for (int mt = 0; mt < 2; mt++) {
                int r = wm*32 + mt*16 + g;
                a[mt][0] = __float_as_uint(A_s[r*L_ALD + ka]);
                a[mt][1] = __float_as_uint(A_s[(r+8)*L_ALD + ka]);
                a[mt][2] = __float_as_uint(A_s[r*L_ALD + ka + 4]);
                a[mt][3] = __float_as_uint(A_s[(r+8)*L_ALD + ka + 4]);
            }
            #pragma unroll
            for (int nt = 0; nt < 4; nt++) {
                int cn = wn*32 + nt*8 + g;
                unsigned b0 = __float_as_uint(B_s[cn*L_BLD + ka]);
                unsigned b1 = __float_as_uint(B_s[cn*L_BLD + ka + 4]);
                #pragma unroll
                for (int mt = 0; mt < 2; mt++) {
                    asm volatile(
                        "mma.sync.aligned.m16n8k8.row.col.f32.tf32.tf32.f32 "
                        "{%0,%1,%2,%3}, {%4,%5,%6,%7}, {%8,%9}, {%0,%1,%2,%3};"
                        : "+f"(acc[mt][nt][0]), "+f"(acc[mt][nt][1]),
                          "+f"(acc[mt][nt][2]), "+f"(acc[mt][nt][3])
                        : "r"(a[mt][0]), "r"(a[mt][1]), "r"(a[mt][2]), "r"(a[mt][3]),
                          "r"(b0), "r"(b1));
                }
            }
        }
        if (kc + 2 < 16) issue(kc + 2);
    }

    #pragma unroll
    for (int mt = 0; mt < 2; mt++) {
        int r0 = wm*32 + mt*16 + g;
        #pragma unroll
        for (int nt = 0; nt < 4; nt++) {
            int c0 = v0 + wn*32 + nt*8 + qt*2;
            if (c0 + 1 < VOCAB) {
                float bo0 = b_out[c0], bo1 = b_out[c0+1];
                logits[(size_t)r0*VOCAB + c0]       = acc[mt][nt][0] + bo0;
                logits[(size_t)r0*VOCAB + c0 + 1]   = acc[mt][nt][1] + bo1;
                logits[(size_t)(r0+8)*VOCAB + c0]     = acc[mt][nt][2] + bo0;
                logits[(size_t)(r0+8)*VOCAB + c0 + 1] = acc[mt][nt][3] + bo1;
            } else if (c0 < VOCAB) {
                float bo0 = b_out[c0];
                logits[(size_t)r0*VOCAB + c0]     = acc[mt][nt][0] + bo0;
                logits[(size_t)(r0+8)*VOCAB + c0] = acc[mt][nt][2] + bo0;
            }
        }
    }
}

// ---------------- kernel 8: per-row logsumexp (1024 thr) -------------------
__global__ void __launch_bounds__(1024) k_lse(const float* __restrict__ logits) {
    int b = blockIdx.x, tid = threadIdx.x;
    __shared__ float red[1024];
    const float* row = logits + (size_t)b*VOCAB;
    float m = -1e30f;
    for (int v = tid; v < VOCAB; v += 1024) m = fmaxf(m, row[v]);
    red[tid] = m; __syncthreads();
    for (int s = 512; s; s >>= 1) { if (tid < s) red[tid] = fmaxf(red[tid], red[tid+s]); __syncthreads(); }
    m = red[0]; __syncthreads();
    float sum = 0.f;
    for (int v = tid; v < VOCAB; v += 1024) sum += expf(row[v] - m);
    red[tid] = sum; __syncthreads();
    for (int s = 512; s; s >>= 1) { if (tid < s) red[tid] += red[tid+s]; __syncthreads(); }
    if (tid == 0) g_lse[b] = m + logf(red[0]);
}

// ---------------- kernel 9: logp = logits - lse ----------------------------
__global__ void __launch_bounds__(256) k_sub(float* __restrict__ logp) {
    int v = blockIdx.x * 256 + threadIdx.x;
    int b = blockIdx.y;
    if (v < VOCAB) logp[(size_t)b*VOCAB + v] -= g_lse[b];
}

// ---------------- launcher -------------------------------------------------
extern "C" void kernel_launch(void* const* d_in, const int* in_sizes, int n_in,
                              void* d_out, int out_size) {
    const int*   ids    = (const int*)d_in[0];
    const float* hidden = (const float*)d_in[1];
    const float* ann    = (const float*)d_in[2];
    const float* emb    = (const float*)d_in[3];
    const float* Wk     = (const float*)d_in[4];
    const float* Wq     = (const float*)d_in[5];
    const float* bk     = (const float*)d_in[6];
    const float* v_attn = (const float*)d_in[7];
    const float* W_ih   = (const float*)d_in[8];
    const float* W_hh   = (const float*)d_in[9];
    const float* b_ih   = (const float*)d_in[10];
    const float* b_hh   = (const float*)d_in[11];
    const float* W_out  = (const float*)d_in[12];
    const float* b_out  = (const float*)d_in[13];

    float* out   = (float*)d_out;
    float* logp  = out;
    float* o_out = out + O_OFF;
    float* a_out = out + A_OFF;

    cudaFuncSetAttribute(k_feat4,      cudaFuncAttributeMaxDynamicSharedMemorySize, FEAT_SMEM);
    cudaFuncSetAttribute(k_logits_tc4, cudaFuncAttributeMaxDynamicSharedMemorySize, LOG_SMEM);

    float* gi_ptr; cudaGetSymbolAddress((void**)&gi_ptr, g_gi);
    float* gh_ptr; cudaGetSymbolAddress((void**)&gh_ptr, g_gh);
    float* gx_ptr; cudaGetSymbolAddress((void**)&gx_ptr, g_x);

    k_wkr       <<<(KEY*HID)/256, 256>>>(Wk);
    k_qw        <<<dim3(HID/256, B), 256>>>(hidden, Wq, bk);
    k_gemm64b   <<<3*HID/64, 256>>>(hidden, W_hh, gh_ptr);     // gh (only needs hidden)
    k_feat4     <<<(B*NK)/64, 256, FEAT_SMEM>>>(ann, v_attn);  // profile slot
    k_attn_sm   <<<B, 256>>>(ids, emb, a_out);
    k_ctx       <<<dim3(B, 8), 256>>>(ann, a_out);
    k_gemm64b   <<<3*HID/64, 256>>>(gx_ptr, W_ih, gi_ptr);     // gi
    k_gates     <<<dim3(HID/256, B), 256>>>(hidden, b_ih, b_hh, o_out);
    k_logits_tc4<<<(VOCAB + 127)/128, 256, LOG_SMEM>>>(W_out, b_out, logp);
    k_lse       <<<B, 1024>>>(logp);
    k_sub       <<<dim3((VOCAB + 255)/256, B), 256>>>(logp);
}

// round 6
// speedup vs baseline: 3.1397x; 1.1344x over previous
#include <cuda_runtime.h>
#include <math.h>
#include <stdint.h>

#define B 64
#define NK 2048
#define HID 1024
#define EMB 512
#define KEY 512
#define VOCAB 50257

#define O_OFF (B*VOCAB)
#define A_OFF (O_OFF + B*HID)

// ---------------- scratch ---------------------------------------------------
__device__ float g_qw[B*HID];
__device__ float g_scores[B*NK];
__device__ float g_x[B*(EMB+KEY)];
__device__ float g_h[B*HID];
__device__ float g_gi[B*3*HID];
__device__ float g_gh[B*3*HID];
__device__ float g_lse[B];
__device__ float g_wkR[KEY*HID];      // Wk tf32-rounded, [k][n] layout

__device__ __forceinline__ float to_tf32(float x) {
    unsigned r;
    asm("cvt.rna.tf32.f32 %0, %1;" : "=r"(r) : "f"(x));
    return __uint_as_float(r);
}
__device__ __forceinline__ uint32_t smem_u32(const void* p) {
    uint32_t a;
    asm("{ .reg .u64 t; cvta.to.shared.u64 t, %1; cvt.u32.u64 %0, t; }" : "=r"(a) : "l"(p));
    return a;
}

// ---------------- kernel: round Wk to tf32 ---------------------------------
__global__ void __launch_bounds__(256) k_wkr(const float* __restrict__ Wk) {
    int i = blockIdx.x * 256 + threadIdx.x;
    g_wkR[i] = to_tf32(Wk[i]);
}

// ---------------- kernel: qw = Q @ Wq + bk ---------------------------------
__global__ void __launch_bounds__(256) k_qw(const float* __restrict__ hidden,
                                            const float* __restrict__ Wq,
                                            const float* __restrict__ bk) {
    int h = blockIdx.x * 256 + threadIdx.x;
    int b = blockIdx.y;
    __shared__ float q_s[HID];
    for (int i = threadIdx.x; i < HID; i += 256) q_s[i] = hidden[b*HID + i];
    __syncthreads();
    float acc = bk[h];
    #pragma unroll 8
    for (int k = 0; k < HID; k++)
        acc = fmaf(q_s[k], Wq[(size_t)k*HID + h], acc);
    g_qw[b*HID + h] = acc;
}

// ---------------- feat GEMM: tf32 mma, 512 threads, cp.async ---------------
// Block: 64 rows A-stationary. 128 its: ncc = it>>5 (256-col chunk of HID),
// kc = it&31 (16-k chunk). 16 warps: wm(2) x 32 rows, wn(8) x 32 cols.
#define AS_LD 516
#define BLD 264
#define B_STG (16*BLD*4)                 // 16896 bytes
#define F_A   0
#define F_B   (64*AS_LD*4)               // 132096
#define F_QW  (F_B + 4*B_STG)            // 199680
#define F_V   (F_QW + HID*4)
#define F_SC  (F_V + HID*4)
#define FEAT_SMEM (F_SC + 64*4)          // 208128

__global__ void __launch_bounds__(512) k_feat5(const float* __restrict__ ann,
                                               const float* __restrict__ v_attn) {
    extern __shared__ char sm[];
    const uint32_t smb = smem_u32(sm);
    float* A_s  = (float*)(sm + F_A);
    float* qw_s = (float*)(sm + F_QW);
    float* v_s  = (float*)(sm + F_V);
    float* sc_s = (float*)(sm + F_SC);

    const int bx   = blockIdx.x;
    const int b    = bx >> 5;
    const int row0 = (bx & 31) * 64;
    const int tid  = threadIdx.x;
    const int lane = tid & 31;
    const int warp = tid >> 5;
    const int wm   = warp >> 3;       // 0..1  (32-row half)
    const int wn   = warp & 7;        // 0..7  (32-col slice of 256-chunk)
    const int g    = lane >> 2;       // 0..7
    const int qt   = lane & 3;        // 0..3

    for (int i = tid; i < HID; i += 512) {
        qw_s[i] = g_qw[b*HID + i];
        v_s[i]  = v_attn[i];
    }
    if (tid < 64) sc_s[tid] = 0.f;

    {
        const float4* src = (const float4*)(ann + ((size_t)b * NK + row0) * KEY);
        for (int i = tid; i < 64*128; i += 512) {
            float4 v4 = src[i];
            v4.x = to_tf32(v4.x); v4.y = to_tf32(v4.y);
            v4.z = to_tf32(v4.z); v4.w = to_tf32(v4.w);
            int r = i >> 7;
            int c = (i & 127) << 2;
            *(float4*)(A_s + r*AS_LD + c) = v4;
        }
    }

    auto issue = [&](int it) {
        int ncc = it >> 5, kc = it & 31, buf = it & 3;
        const float* src = g_wkR + (size_t)(kc*16)*HID + ncc*256;
        #pragma unroll
        for (int u = 0; u < 2; u++) {
            int gi = tid + u*512;
            int r = gi >> 6, c4 = gi & 63;
            uint32_t dst = smb + F_B + buf*B_STG + (uint32_t)(r*BLD + c4*4)*4;
            const float* s = src + (size_t)r*HID + c4*4;
            asm volatile("cp.async.cg.shared.global [%0], [%1], 16;" :: "r"(dst), "l"(s));
        }
        asm volatile("cp.async.commit_group;" ::: "memory");
    };

    issue(0); issue(1); issue(2);

    float rs[2][2] = {{0.f,0.f},{0.f,0.f}};
    float acc[2][4][4];

    for (int it = 0; it < 128; it++) {
        const int buf = it & 3;
        const int kc  = it & 31;
        asm volatile("cp.async.wait_group 2;" ::: "memory");
        __syncthreads();

        if (kc == 0) {
            #pragma unroll
            for (int mt = 0; mt < 2; mt++)
                #pragma unroll
                for (int nt = 0; nt < 4; nt++)
                    #pragma unroll
                    for (int i = 0; i < 4; i++) acc[mt][nt][i] = 0.f;
        }

        const float* Bst = (const float*)(sm + F_B + buf*B_STG);
        #pragma unroll
        for (int kk = 0; kk < 2; kk++) {
            const int ka = kc*16 + kk*8 + qt;
            unsigned a[2][4];
            #pragma unroll
            for (int mt = 0; mt < 2; mt++) {
                int r = wm*32 + mt*16 + g;
                a[mt][0] = __float_as_uint(A_s[r*AS_LD + ka]);
                a[mt][1] = __float_as_uint(A_s[(r+8)*AS_LD + ka]);
                a[mt][2] = __float_as_uint(A_s[r*AS_LD + ka + 4]);
                a[mt][3] = __float_as_uint(A_s[(r+8)*AS_LD + ka + 4]);
            }
            #pragma unroll
            for (int nt = 0; nt < 4; nt++) {
                int cn = wn*32 + nt*8 + g;
                unsigned b0 = __float_as_uint(Bst[(kk*8 + qt)*BLD + cn]);
                unsigned b1 = __float_as_uint(Bst[(kk*8 + qt + 4)*BLD + cn]);
                #pragma unroll
                for (int mt = 0; mt < 2; mt++) {
                    asm volatile(
                        "mma.sync.aligned.m16n8k8.row.col.f32.tf32.tf32.f32 "
                        "{%0,%1,%2,%3}, {%4,%5,%6,%7}, {%8,%9}, {%0,%1,%2,%3};"
                        : "+f"(acc[mt][nt][0]), "+f"(acc[mt][nt][1]),
                          "+f"(acc[mt][nt][2]), "+f"(acc[mt][nt][3])
                        : "r"(a[mt][0]), "r"(a[mt][1]), "r"(a[mt][2]), "r"(a[mt][3]),
                          "r"(b0), "r"(b1));
                }
            }
        }

        if (kc == 31) {
            const int ncc = it >> 5;
            #pragma unroll
            for (int mt = 0; mt < 2; mt++)
                #pragma unroll
                for (int nt = 0; nt < 4; nt++) {
                    int h0 = ncc*256 + wn*32 + nt*8 + qt*2;
                    float v0 = v_s[h0],     q0u = qw_s[h0];
                    float v1 = v_s[h0 + 1], q1u = qw_s[h0 + 1];
                    rs[mt][0] = fmaf(v0, tanhf(acc[mt][nt][0] + q0u), rs[mt][0]);
                    rs[mt][0] = fmaf(v1, tanhf(acc[mt][nt][1] + q1u), rs[mt][0]);
                    rs[mt][1] = fmaf(v0, tanhf(acc[mt][nt][2] + q0u), rs[mt][1]);
                    rs[mt][1] = fmaf(v1, tanhf(acc[mt][nt][3] + q1u), rs[mt][1]);
                }
        }

        if (it + 3 < 128) issue(it + 3);
    }

    #pragma unroll
    for (int mt = 0; mt < 2; mt++)
        #pragma unroll
        for (int up = 0; up < 2; up++) {
            float p = rs[mt][up];
            p += __shfl_xor_sync(0xffffffffu, p, 1);
            p += __shfl_xor_sync(0xffffffffu, p, 2);
            if (qt == 0)
                atomicAdd(&sc_s[wm*32 + mt*16 + up*8 + g], p);
        }
    __syncthreads();
    if (tid < 64) g_scores[(size_t)b*NK + row0 + tid] = sc_s[tid];
}

// ---------------- softmax + emb copy ---------------------------------------
__global__ void __launch_bounds__(256) k_attn_sm(const int* __restrict__ ids,
                                                 const float* __restrict__ emb_table,
                                                 float* __restrict__ a_out) {
    int b = blockIdx.x;
    int tid = threadIdx.x;
    __shared__ float sc[NK];
    __shared__ float red[256];

    float m = -1e30f;
    for (int i = tid; i < NK; i += 256) {
        float v = g_scores[b*NK + i];
        sc[i] = v;
        m = fmaxf(m, v);
    }
    red[tid] = m; __syncthreads();
    for (int s = 128; s; s >>= 1) { if (tid < s) red[tid] = fmaxf(red[tid], red[tid+s]); __syncthreads(); }
    m = red[0]; __syncthreads();

    float sum = 0.f;
    for (int i = tid; i < NK; i += 256) { float e = expf(sc[i] - m); sc[i] = e; sum += e; }
    red[tid] = sum; __syncthreads();
    for (int s = 128; s; s >>= 1) { if (tid < s) red[tid] += red[tid+s]; __syncthreads(); }
    float inv = 1.f / red[0];
    __syncthreads();

    for (int i = tid; i < NK; i += 256)
        a_out[(size_t)b*NK + i] = sc[i] * inv;

    int id = ids[b];
    for (int k = tid; k < EMB; k += 256)
        g_x[b*(EMB+KEY) + k] = emb_table[(size_t)id*EMB + k];
}

// ---------------- context = a . ann ----------------------------------------
__global__ void __launch_bounds__(256) k_ctx(const float* __restrict__ ann,
                                             const float* __restrict__ a_out) {
    int b = blockIdx.x;
    int p = blockIdx.y;
    int tid = threadIdx.x;
    int c  = tid & 63;
    int rg = tid >> 6;
    __shared__ float part[4][64];

    const float* ab = ann + (size_t)b*NK*KEY + p*64 + c;
    const float* av = a_out + (size_t)b*NK;
    float acc = 0.f;
    for (int n = rg; n < NK; n += 4)
        acc = fmaf(av[n], ab[(size_t)n*KEY], acc);
    part[rg][c] = acc;
    __syncthreads();
    if (rg == 0)
        g_x[b*(EMB+KEY) + EMB + p*64 + c] =
            part[0][c] + part[1][c] + part[2][c] + part[3][c];
}

// ---------------- shared tf32 GEMM body: C[64,128-tile] = A @ W^T ----------
#define L_ALD 68
#define L_BLD 68
#define L_ASTG (64*L_ALD*4)
#define L_BSTG (128*L_BLD*4)
#define L_STG  (L_ASTG + L_BSTG)
#define LOG_SMEM (3*L_STG)               // 156672

__device__ __forceinline__ void gemm_tc_body(const float* __restrict__ Amat,
                                             const float* __restrict__ W,
                                             int v0, int N, uint32_t smb, char* sm,
                                             float acc[2][4][4]) {
    const int tid = threadIdx.x;
    const int lane = tid & 31;
    const int warp = tid >> 5;
    const int wm = warp >> 2;
    const int wn = warp & 3;
    const int g  = lane >> 2;
    const int qt = lane & 3;

    auto issue = [&](int kc) {
        int buf = kc % 3;
        {
            const float* src = Amat + kc*64;
            #pragma unroll
            for (int u = 0; u < 4; u++) {
                int gi = tid + u*256;
                int r = gi >> 4, c4 = gi & 15;
                uint32_t dst = smb + buf*L_STG + (uint32_t)(r*L_ALD + c4*4)*4;
                const float* s = src + (size_t)r*HID + c4*4;
                asm volatile("cp.async.cg.shared.global [%0], [%1], 16;" :: "r"(dst), "l"(s));
            }
        }
        {
            #pragma unroll
            for (int u = 0; u < 8; u++) {
                int gi = tid + u*256;
                int r = gi >> 4, c4 = gi & 15;
                int v = v0 + r;
                uint32_t dst = smb + buf*L_STG + L_ASTG + (uint32_t)(r*L_BLD + c4*4)*4;
                const float* s = (v < N) ? (W + (size_t)v*HID + kc*64 + c4*4) : W;
                unsigned sz = (v < N) ? 16u : 0u;
                asm volatile("cp.async.cg.shared.global [%0], [%1], 16, %2;"
                             :: "r"(dst), "l"(s), "r"(sz));
            }
        }
        asm volatile("cp.async.commit_group;" ::: "memory");
    };

    issue(0); issue(1);

    #pragma unroll
    for (int mt = 0; mt < 2; mt++)
        #pragma unroll
        for (int nt = 0; nt < 4; nt++)
            #pragma unroll
            for (int i = 0; i < 4; i++) acc[mt][nt][i] = 0.f;

    for (int kc = 0; kc < 16; kc++) {
        const int buf = kc % 3;
        asm volatile("cp.async.wait_group 1;" ::: "memory");
        __syncthreads();

        const float* A_s = (const float*)(sm + buf*L_STG);
        const float* B_s = (const float*)(sm + buf*L_STG + L_ASTG);
        #pragma unroll
        for (int kk = 0; kk < 8; kk++) {
            const int ka = kk*8 + qt;
            unsigned a[2][4];
            #pragma unroll
            for (int mt = 0; mt < 2; mt++) {
                int r = wm*32 + mt*16 + g;
                a[mt][0] = __float_as_uint(A_s[r*L_ALD + ka]);
                a[mt][1] = __float_as_uint(A_s[(r+8)*L_ALD + ka]);
                a[mt][2] = __float_as_uint(A_s[r*L_ALD + ka + 4]);
                a[mt][3] = __float_as_uint(A_s[(r+8)*L_ALD + ka + 4]);
            }
            #pragma unroll
            for (int nt = 0; nt < 4; nt++) {
                int cn = wn*32 + nt*8 + g;
                unsigned b0 = __float_as_uint(B_s[cn*L_BLD + ka]);
                unsigned b1 = __float_as_uint(B_s[cn*L_BLD + ka + 4]);
                #pragma unroll
                for (int mt = 0; mt < 2; mt++) {
                    asm volatile(
                        "mma.sync.aligned.m16n8k8.row.col.f32.tf32.tf32.f32 "
                        "{%0,%1,%2,%3}, {%4,%5,%6,%7}, {%8,%9}, {%0,%1,%2,%3};"
                        : "+f"(acc[mt][nt][0]), "+f"(acc[mt][nt][1]),
                          "+f"(acc[mt][nt][2]), "+f"(acc[mt][nt][3])
                        : "r"(a[mt][0]), "r"(a[mt][1]), "r"(a[mt][2]), "r"(a[mt][3]),
                          "r"(b0), "r"(b1));
                }
            }
        }
        if (kc + 2 < 16) issue(kc + 2);
    }
}

// gi/gh GEMM: `which` selects operand set (1: gh from hidden/W_hh, 0: gi).
__global__ void __launch_bounds__(256) k_gru_tc(const float* __restrict__ hidden,
                                                const float* __restrict__ W_ih,
                                                const float* __restrict__ W_hh,
                                                int which) {
    extern __shared__ char sm[];
    const uint32_t smb = smem_u32(sm);
    const float* Amat = which ? hidden : g_x;
    const float* W    = which ? W_hh   : W_ih;
    float*       C    = which ? g_gh   : g_gi;
    const int v0 = blockIdx.x * 128;

    float acc[2][4][4];
    gemm_tc_body(Amat, W, v0, 3*HID, smb, sm, acc);

    const int lane = threadIdx.x & 31;
    const int warp = threadIdx.x >> 5;
    const int wm = warp >> 2, wn = warp & 3;
    const int g = lane >> 2, qt = lane & 3;
    #pragma unroll
    for (int mt = 0; mt < 2; mt++) {
        int r0 = wm*32 + mt*16 + g;
        #pragma unroll
        for (int nt = 0; nt < 4; nt++) {
            int c0 = v0 + wn*32 + nt*8 + qt*2;
            C[(size_t)r0*3*HID + c0]         = acc[mt][nt][0];
            C[(size_t)r0*3*HID + c0 + 1]     = acc[mt][nt][1];
            C[(size_t)(r0+8)*3*HID + c0]     = acc[mt][nt][2];
            C[(size_t)(r0+8)*3*HID + c0 + 1] = acc[mt][nt][3];
        }
    }
}

// logits GEMM (bias added)
__global__ void __launch_bounds__(256) k_logits_tc5(const float* __restrict__ W_out,
                                                    const float* __restrict__ b_out,
                                                    float* __restrict__ logits) {
    extern __shared__ char sm[];
    const uint32_t smb = smem_u32(sm);
    const int v0 = blockIdx.x * 128;

    float acc[2][4][4];
    gemm_tc_body(g_h, W_out, v0, VOCAB, smb, sm, acc);

    const int lane = threadIdx.x & 31;
    const int warp = threadIdx.x >> 5;
    const int wm = warp >> 2, wn = warp & 3;
    const int g = lane >> 2, qt = lane & 3;
    #pragma unroll
    for (int mt = 0; mt < 2; mt++) {
        int r0 = wm*32 + mt*16 + g;
        #pragma unroll
        for (int nt = 0; nt < 4; nt++) {
            int c0 = v0 + wn*32 + nt*8 + qt*2;
            if (c0 + 1 < VOCAB) {
                float bo0 = b_out[c0], bo1 = b_out[c0+1];
                logits[(size_t)r0*VOCAB + c0]         = acc[mt][nt][0] + bo0;
                logits[(size_t)r0*VOCAB + c0 + 1]     = acc[mt][nt][1] + bo1;
                logits[(size_t)(r0+8)*VOCAB + c0]     = acc[mt][nt][2] + bo0;
                logits[(size_t)(r0+8)*VOCAB + c0 + 1] = acc[mt][nt][3] + bo1;
            } else if (c0 < VOCAB) {
                float bo0 = b_out[c0];
                logits[(size_t)r0*VOCAB + c0]     = acc[mt][nt][0] + bo0;
                logits[(size_t)(r0+8)*VOCAB + c0] = acc[mt][nt][2] + bo0;
            }
        }
    }
}

// ---------------- GRU gates ------------------------------------------------
__global__ void __launch_bounds__(256) k_gates(const float* __restrict__ hidden,
                                               const float* __restrict__ b_ih,
                                               const float* __restrict__ b_hh,
                                               float* __restrict__ o_out) {
    int j = blockIdx.x * 256 + threadIdx.x;
    int b = blockIdx.y;
    float ir  = g_gi[b*3*HID + j]         + b_ih[j];
    float iz  = g_gi[b*3*HID + HID + j]   + b_ih[HID + j];
    float inn = g_gi[b*3*HID + 2*HID + j] + b_ih[2*HID + j];
    float hr  = g_gh[b*3*HID + j]         + b_hh[j];
    float hz  = g_gh[b*3*HID + HID + j]   + b_hh[HID + j];
    float hn  = g_gh[b*3*HID + 2*HID + j] + b_hh[2*HID + j];
    float r = 1.f / (1.f + expf(-(ir + hr)));
    float z = 1.f / (1.f + expf(-(iz + hz)));
    float n = tanhf(inn + r * hn);
    float q = hidden[b*HID + j];
    float h = (1.f - z) * n + z * q;
    g_h[b*HID + j]   = h;
    o_out[b*HID + j] = h;
}

// ---------------- logsumexp + subtract -------------------------------------
__global__ void __launch_bounds__(1024) k_lse(const float* __restrict__ logits) {
    int b = blockIdx.x, tid = threadIdx.x;
    __shared__ float red[1024];
    const float* row = logits + (size_t)b*VOCAB;
    float m = -1e30f;
    for (int v = tid; v < VOCAB; v += 1024) m = fmaxf(m, row[v]);
    red[tid] = m; __syncthreads();
    for (int s = 512; s; s >>= 1) { if (tid < s) red[tid] = fmaxf(red[tid], red[tid+s]); __syncthreads(); }
    m = red[0]; __syncthreads();
    float sum = 0.f;
    for (int v = tid; v < VOCAB; v += 1024) sum += expf(row[v] - m);
    red[tid] = sum; __syncthreads();
    for (int s = 512; s; s >>= 1) { if (tid < s) red[tid] += red[tid+s]; __syncthreads(); }
    if (tid == 0) g_lse[b] = m + logf(red[0]);
}

__global__ void __launch_bounds__(256) k_sub(float* __restrict__ logp) {
    int v = blockIdx.x * 256 + threadIdx.x;
    int b = blockIdx.y;
    if (v < VOCAB) logp[(size_t)b*VOCAB + v] -= g_lse[b];
}

// ---------------- launcher -------------------------------------------------
extern "C" void kernel_launch(void* const* d_in, const int* in_sizes, int n_in,
                              void* d_out, int out_size) {
    const int*   ids    = (const int*)d_in[0];
    const float* hidden = (const float*)d_in[1];
    const float* ann    = (const float*)d_in[2];
    const float* emb    = (const float*)d_in[3];
    const float* Wk     = (const float*)d_in[4];
    const float* Wq     = (const float*)d_in[5];
    const float* bk     = (const float*)d_in[6];
    const float* v_attn = (const float*)d_in[7];
    const float* W_ih   = (const float*)d_in[8];
    const float* W_hh   = (const float*)d_in[9];
    const float* b_ih   = (const float*)d_in[10];
    const float* b_hh   = (const float*)d_in[11];
    const float* W_out  = (const float*)d_in[12];
    const float* b_out  = (const float*)d_in[13];

    float* out   = (float*)d_out;
    float* logp  = out;
    float* o_out = out + O_OFF;
    float* a_out = out + A_OFF;

    cudaFuncSetAttribute(k_feat5,      cudaFuncAttributeMaxDynamicSharedMemorySize, FEAT_SMEM);
    cudaFuncSetAttribute(k_gru_tc,     cudaFuncAttributeMaxDynamicSharedMemorySize, LOG_SMEM);
    cudaFuncSetAttribute(k_logits_tc5, cudaFuncAttributeMaxDynamicSharedMemorySize, LOG_SMEM);

    k_wkr       <<<(KEY*HID)/256, 256>>>(Wk);
    k_qw        <<<dim3(HID/256, B), 256>>>(hidden, Wq, bk);
    k_gru_tc    <<<3*HID/128, 256, LOG_SMEM>>>(hidden, W_ih, W_hh, 1);  // gh
    k_feat5     <<<(B*NK)/64, 512, FEAT_SMEM>>>(ann, v_attn);           // ncu slot
    k_attn_sm   <<<B, 256>>>(ids, emb, a_out);
    k_ctx       <<<dim3(B, 8), 256>>>(ann, a_out);
    k_gru_tc    <<<3*HID/128, 256, LOG_SMEM>>>(hidden, W_ih, W_hh, 0);  // gi
    k_gates     <<<dim3(HID/256, B), 256>>>(hidden, b_ih, b_hh, o_out);
    k_logits_tc5<<<(VOCAB + 127)/128, 256, LOG_SMEM>>>(W_out, b_out, logp);
    k_lse       <<<B, 1024>>>(logp);
    k_sub       <<<dim3((VOCAB + 255)/256, B), 256>>>(logp);
}